// round 9
// baseline (speedup 1.0000x reference)
#include <cuda_runtime.h>
#include <math.h>
#include <cstdint>
#include <cstddef>

// ---------------- problem constants ----------------
#define T_TOK   2048
#define DIMX    2048
#define QKVC    3072      // (32 + 2*8) * 64
#define NKV     8
#define WIN     128
#define TQ      16
#define KROWS   143

// Scratch (no allocs allowed)
__device__ float g_qkv[(size_t)T_TOK * QKVC];
__device__ float g_attn[(size_t)T_TOK * DIMX];
__device__ float g_xc[(size_t)T_TOK * DIMX];      // tf32-rounded x
__device__ float g_wqkvc[(size_t)QKVC * DIMX];    // tf32-rounded Wqkv
__device__ float g_woc[(size_t)DIMX * DIMX];      // tf32-rounded Wo

// ---------------- helpers ----------------
__device__ __forceinline__ uint32_t smem_u32(const void* p) {
    uint32_t a;
    asm("{ .reg .u64 t; cvta.to.shared.u64 t, %1; cvt.u32.u64 %0, t; }"
        : "=r"(a) : "l"(p));
    return a;
}
__device__ __forceinline__ float f2tf32f(float f) {
    uint32_t r;
    asm("cvt.rna.tf32.f32 %0, %1;" : "=r"(r) : "f"(f));
    return __uint_as_float(r);
}
__device__ __forceinline__ void mma_tf32(float* d, const uint32_t* a,
                                         const uint32_t* b) {
    asm volatile(
        "mma.sync.aligned.m16n8k8.row.col.f32.tf32.tf32.f32 "
        "{%0,%1,%2,%3}, {%4,%5,%6,%7}, {%8,%9}, {%0,%1,%2,%3};"
        : "+f"(d[0]), "+f"(d[1]), "+f"(d[2]), "+f"(d[3])
        : "r"(a[0]), "r"(a[1]), "r"(a[2]), "r"(a[3]), "r"(b[0]), "r"(b[1]));
}
__device__ __forceinline__ void ldsm_x4(uint32_t* r, uint32_t addr) {
    asm volatile(
        "ldmatrix.sync.aligned.m8n8.x4.shared.b16 {%0,%1,%2,%3}, [%4];"
        : "=r"(r[0]), "=r"(r[1]), "=r"(r[2]), "=r"(r[3]) : "r"(addr));
}

// ---------------- tf32 pre-round pass ----------------
__global__ void cvt_tf32_kernel(const float* __restrict__ in,
                                float* __restrict__ out, int n4)
{
    int i = blockIdx.x * blockDim.x + threadIdx.x;
    if (i < n4) {
        float4 v = *(const float4*)(in + (size_t)i * 4);
        v.x = f2tf32f(v.x); v.y = f2tf32f(v.y);
        v.z = f2tf32f(v.z); v.w = f2tf32f(v.w);
        *(float4*)(out + (size_t)i * 4) = v;
    }
}

// ---------------- tf32 mma.sync GEMM (ldmatrix + frag pipelining) -----------
// C[M, Ntot] = A[M, K] * B[Ntot, K]^T + bias.  Inputs MUST be tf32-pre-rounded.
// CTA tile 128x128x32, 3-stage cp.async pipeline, 256 threads, 2 CTAs/SM.
#define GBM 128
#define GBN 128
#define GBK 32
#define PADW 36                    // 144B row stride; 144%128==16 -> LDSM conflict-free
#define SSTG (GBM * PADW * 2)      // floats per stage (A + B) = 9216
#define GEMM_SMEM (3 * SSTG * 4)   // 110592 bytes

template <bool DO_ROPE>
__global__ __launch_bounds__(256, 2)     // force <=128 regs -> 2 CTAs/SM
void gemm_mma_tf32(const float* __restrict__ A, const float* __restrict__ B,
                   const float* __restrict__ bias, float* __restrict__ C,
                   int Ntot, int K,
                   const float* __restrict__ cosT, const float* __restrict__ sinT)
{
    extern __shared__ float smf[];
    const uint32_t sbase = smem_u32(smf);

    const int tid  = threadIdx.x;
    const int lane = tid & 31;
    const int wid  = tid >> 5;
    const int warpM = wid & 3;       // 4 warps along M (32 rows each)
    const int warpN = wid >> 2;      // 2 warps along N (64 cols each)
    const int gid = lane >> 2;       // 0..7
    const int tig = lane & 3;        // 0..3

    const int m0 = blockIdx.y * GBM;
    const int n0 = blockIdx.x * GBN;
    const int niter = K / GBK;       // 64

    const float* Ag = A + (size_t)m0 * K;
    const float* Bg = B + (size_t)n0 * K;

    const int r0 = tid >> 3;         // 0..31
    const int c4 = (tid & 7) * 4;    // 0..28

    // ldmatrix per-lane address offsets (bytes, relative to stage base)
    const int q = lane >> 3;                         // 0..3 (tile id in x4)
    const int arow = ((q & 1) << 3) + (lane & 7);    // 0..15
    const int akof = (q >> 1) << 2;                  // 0 or 4
    const int brow = ((q >> 1) << 3) + (lane & 7);   // 0..15
    const int bkof = (q & 1) << 2;                   // 0 or 4
    const uint32_t a_off = (uint32_t)(((warpM * 32 + arow) * PADW + akof) * 4);
    const uint32_t b_off = (uint32_t)((GBM * PADW + (warpN * 64 + brow) * PADW + bkof) * 4);

    float acc[2][8][4];
#pragma unroll
    for (int mt = 0; mt < 2; mt++)
#pragma unroll
        for (int nt = 0; nt < 8; nt++)
#pragma unroll
            for (int z = 0; z < 4; z++) acc[mt][nt][z] = 0.f;

    auto issue = [&](int kt, int s) {
        if (kt < niter) {
            uint32_t abase = sbase + (uint32_t)(s * SSTG + r0 * PADW + c4) * 4;
            const float* ap = Ag + (size_t)r0 * K + kt * GBK + c4;
            const float* bp = Bg + (size_t)r0 * K + kt * GBK + c4;
            uint32_t bbase = abase + GBM * PADW * 4;
#pragma unroll
            for (int i = 0; i < 4; i++) {
                asm volatile("cp.async.cg.shared.global [%0], [%1], 16;"
                             :: "r"(abase + i * 32 * PADW * 4),
                                "l"(ap + (size_t)i * 32 * K) : "memory");
                asm volatile("cp.async.cg.shared.global [%0], [%1], 16;"
                             :: "r"(bbase + i * 32 * PADW * 4),
                                "l"(bp + (size_t)i * 32 * K) : "memory");
            }
        }
        asm volatile("cp.async.commit_group;" ::: "memory");
    };

    issue(0, 0);
    issue(1, 1);

    for (int it = 0; it < niter; it++) {
        asm volatile("cp.async.wait_group 1;" ::: "memory");
        __syncthreads();                 // single barrier per iter

        // prefetch next stage immediately (stage (it+2)%3 == (it-1)%3: safe,
        // the barrier above proves everyone finished reading it)
        issue(it + 2, (it + 2) % 3);

        const uint32_t stg = sbase + (uint32_t)((it % 3) * SSTG) * 4;
        const uint32_t aB = stg + a_off;
        const uint32_t bB = stg + b_off;

        // software-pipelined fragments: load ks+1 while computing ks
        uint32_t afr[2][2][4];
        uint32_t bfr[2][4][4];
        ldsm_x4(afr[0][0], aB);
        ldsm_x4(afr[0][1], aB + 16 * PADW * 4);
        ldsm_x4(bfr[0][0], bB);
        ldsm_x4(bfr[0][1], bB + 16 * PADW * 4);
        ldsm_x4(bfr[0][2], bB + 32 * PADW * 4);
        ldsm_x4(bfr[0][3], bB + 48 * PADW * 4);

#pragma unroll
        for (int ks = 0; ks < 4; ks++) {
            const int cur = ks & 1, nxt = cur ^ 1;
            if (ks < 3) {
                const uint32_t kb = (uint32_t)(ks + 1) * 32;
                ldsm_x4(afr[nxt][0], aB + kb);
                ldsm_x4(afr[nxt][1], aB + kb + 16 * PADW * 4);
                ldsm_x4(bfr[nxt][0], bB + kb);
                ldsm_x4(bfr[nxt][1], bB + kb + 16 * PADW * 4);
                ldsm_x4(bfr[nxt][2], bB + kb + 32 * PADW * 4);
                ldsm_x4(bfr[nxt][3], bB + kb + 48 * PADW * 4);
            }
#pragma unroll
            for (int mt = 0; mt < 2; mt++)
#pragma unroll
                for (int p = 0; p < 4; p++) {
                    mma_tf32(acc[mt][2 * p + 0], afr[cur][mt], &bfr[cur][p][0]);
                    mma_tf32(acc[mt][2 * p + 1], afr[cur][mt], &bfr[cur][p][2]);
                }
        }
    }

    // ---- epilogue: bias + optional fused RoPE (cols < 2560 are q/k heads) --
    const bool rope_tile = DO_ROPE && (n0 < 2560);
#pragma unroll
    for (int mt = 0; mt < 2; mt++) {
        int row = m0 + warpM * 32 + mt * 16 + gid;   // token for z0,z1; row+8 for z2,z3
#pragma unroll
        for (int np = 0; np < 4; np++) {
            int colL = n0 + warpN * 64 + np * 8 + 2 * tig;   // colL % 64 in [0,31)
            int colH = colL + 32;
            float L[4], H[4];
#pragma unroll
            for (int z = 0; z < 4; z++) {
                L[z] = acc[mt][np][z]     + __ldg(&bias[colL + (z & 1)]);
                H[z] = acc[mt][np + 4][z] + __ldg(&bias[colH + (z & 1)]);
            }
            if (rope_tile) {
                int dl = colL & 63;                       // 0..30
                const float* c1 = cosT + (size_t)row * 64;
                const float* s1 = sinT + (size_t)row * 64;
                const float* c2 = c1 + 8 * 64;
                const float* s2 = s1 + 8 * 64;
#pragma unroll
                for (int z = 0; z < 4; z++) {
                    const float* cc = (z < 2) ? c1 : c2;
                    const float* ss = (z < 2) ? s1 : s2;
                    int d = dl + (z & 1);
                    float lo = L[z], hi = H[z];
                    L[z] = lo * cc[d]      - hi * ss[d];
                    H[z] = hi * cc[d + 32] + lo * ss[d + 32];
                }
            }
            *(float2*)(C + (size_t)row * Ntot + colL)       = make_float2(L[0], L[1]);
            *(float2*)(C + (size_t)(row + 8) * Ntot + colL) = make_float2(L[2], L[3]);
            *(float2*)(C + (size_t)row * Ntot + colH)       = make_float2(H[0], H[1]);
            *(float2*)(C + (size_t)(row + 8) * Ntot + colH) = make_float2(H[2], H[3]);
        }
    }
}

// ---------------- SWA (emits tf32-rounded attn for GEMM2) ----------------
#define ATTN_SMEM_FLOATS (64*144 + 144*64 + 64*64 + 64*129 + 64)

__global__ __launch_bounds__(256, 1)
void swa_kernel(const float* __restrict__ sinks)
{
    extern __shared__ float sm[];
    float* Kt  = sm;
    float* V   = Kt + 64 * 144;
    float* Qt  = V  + 144 * 64;
    float* S   = Qt + 64 * 64;
    float* den = S  + 64 * 129;

    const int tid = threadIdx.x;
    const int t0  = blockIdx.x * TQ;
    const int kvh = blockIdx.y;

    for (int idx = tid; idx < KROWS * 64; idx += 256) {
        int u = idx >> 6, d = idx & 63;
        int j = t0 - 127 + u;
        float kv = 0.f, vv = 0.f;
        if (j >= 0) {
            const float* r = g_qkv + (size_t)j * QKVC;
            kv = r[2048 + kvh * 64 + d];
            vv = r[2560 + kvh * 64 + d];
        }
        Kt[d * 144 + u] = kv;
        V[u * 64 + d]   = vv;
    }
    for (int idx = tid; idx < 64 * 64; idx += 256) {
        int r = idx >> 6, d = idx & 63;
        int i = r >> 2, g = r & 3;
        Qt[d * 64 + r] =
            g_qkv[(size_t)(t0 + i) * QKVC + (kvh * 4 + g) * 64 + d] * 0.125f;
    }
    __syncthreads();

    {
        const int c = tid & 31;
#pragma unroll
        for (int half = 0; half < 2; half++) {
            const int a = (tid >> 5) + half * 8;
            float acc[16];
#pragma unroll
            for (int z = 0; z < 16; z++) acc[z] = 0.f;
#pragma unroll 8
            for (int d = 0; d < 64; d++) {
                float q0 = Qt[d * 64 + 4 * a + 0];
                float q1 = Qt[d * 64 + 4 * a + 1];
                float q2 = Qt[d * 64 + 4 * a + 2];
                float q3 = Qt[d * 64 + 4 * a + 3];
                float k0 = Kt[d * 144 + a + c];
                float k1 = Kt[d * 144 + a + c + 32];
                float k2 = Kt[d * 144 + a + c + 64];
                float k3 = Kt[d * 144 + a + c + 96];
                acc[0]  += q0 * k0; acc[1]  += q0 * k1; acc[2]  += q0 * k2; acc[3]  += q0 * k3;
                acc[4]  += q1 * k0; acc[5]  += q1 * k1; acc[6]  += q1 * k2; acc[7]  += q1 * k3;
                acc[8]  += q2 * k0; acc[9]  += q2 * k1; acc[10] += q2 * k2; acc[11] += q2 * k3;
                acc[12] += q3 * k0; acc[13] += q3 * k1; acc[14] += q3 * k2; acc[15] += q3 * k3;
            }
#pragma unroll
            for (int g = 0; g < 4; g++)
#pragma unroll
                for (int kk = 0; kk < 4; kk++)
                    S[(4 * a + g) * 129 + c + kk * 32] = acc[g * 4 + kk];
        }
    }
    __syncthreads();

    {
        const int warp = tid >> 5, lane = tid & 31;
        for (int rr = 0; rr < 8; rr++) {
            int r = warp * 8 + rr;
            int i = r >> 2, g = r & 3;
            int t = t0 + i;
            int wmin = 127 - t;
            float s[4];
#pragma unroll
            for (int kk = 0; kk < 4; kk++) {
                int w = lane + kk * 32;
                float v = S[r * 129 + w];
                s[kk] = (w < wmin) ? -1e30f : v;
            }
            float m = fmaxf(fmaxf(s[0], s[1]), fmaxf(s[2], s[3]));
#pragma unroll
            for (int o = 16; o; o >>= 1)
                m = fmaxf(m, __shfl_xor_sync(0xffffffffu, m, o));
            float snk = __ldg(&sinks[kvh * 4 + g]);
            m = fmaxf(m, snk);
            float sum = 0.f;
#pragma unroll
            for (int kk = 0; kk < 4; kk++) {
                float e = __expf(s[kk] - m);
                S[r * 129 + lane + kk * 32] = e;
                sum += e;
            }
#pragma unroll
            for (int o = 16; o; o >>= 1)
                sum += __shfl_xor_sync(0xffffffffu, sum, o);
            sum += __expf(snk - m);
            if (lane == 0) den[r] = 1.0f / sum;
        }
    }
    __syncthreads();

    {
        const int b = tid >> 4;
        const int e = tid & 15;
        float o_[4][4];
#pragma unroll
        for (int g = 0; g < 4; g++)
#pragma unroll
            for (int z = 0; z < 4; z++) o_[g][z] = 0.f;

        for (int w = 0; w < 128; w++) {
            float4 v4 = *(const float4*)(V + (b + w) * 64 + e * 4);
#pragma unroll
            for (int g = 0; g < 4; g++) {
                float p = S[(4 * b + g) * 129 + w];
                o_[g][0] += p * v4.x;
                o_[g][1] += p * v4.y;
                o_[g][2] += p * v4.z;
                o_[g][3] += p * v4.w;
            }
        }
        const int t = t0 + b;
#pragma unroll
        for (int g = 0; g < 4; g++) {
            float inv = den[4 * b + g];
            float4 r;
            r.x = f2tf32f(o_[g][0] * inv);
            r.y = f2tf32f(o_[g][1] * inv);
            r.z = f2tf32f(o_[g][2] * inv);
            r.w = f2tf32f(o_[g][3] * inv);
            *(float4*)(g_attn + (size_t)t * DIMX + (kvh * 4 + g) * 64 + e * 4) = r;
        }
    }
}

// ---------------- host ----------------
extern "C" void kernel_launch(void* const* d_in, const int* in_sizes, int n_in,
                              void* d_out, int out_size)
{
    (void)in_sizes; (void)n_in; (void)out_size;
    const float* x     = (const float*)d_in[0];
    const float* cosT  = (const float*)d_in[1];
    const float* sinT  = (const float*)d_in[2];
    const float* Wqkv  = (const float*)d_in[3];
    const float* bqkv  = (const float*)d_in[4];
    const float* Wo    = (const float*)d_in[5];
    const float* bo    = (const float*)d_in[6];
    const float* sinks = (const float*)d_in[7];
    float* out = (float*)d_out;

    float *qkv = nullptr, *att = nullptr;
    float *xc = nullptr, *wqkvc = nullptr, *woc = nullptr;
    cudaGetSymbolAddress((void**)&qkv,   g_qkv);
    cudaGetSymbolAddress((void**)&att,   g_attn);
    cudaGetSymbolAddress((void**)&xc,    g_xc);
    cudaGetSymbolAddress((void**)&wqkvc, g_wqkvc);
    cudaGetSymbolAddress((void**)&woc,   g_woc);

    cudaFuncSetAttribute(gemm_mma_tf32<true>,
                         cudaFuncAttributeMaxDynamicSharedMemorySize, GEMM_SMEM);
    cudaFuncSetAttribute(gemm_mma_tf32<false>,
                         cudaFuncAttributeMaxDynamicSharedMemorySize, GEMM_SMEM);
    const int attn_smem = ATTN_SMEM_FLOATS * 4;
    cudaFuncSetAttribute(swa_kernel,
                         cudaFuncAttributeMaxDynamicSharedMemorySize, attn_smem);

    // 0) tf32 pre-rounding passes
    cvt_tf32_kernel<<<(T_TOK * DIMX / 4 + 255) / 256, 256>>>(x,    xc,    T_TOK * DIMX / 4);
    cvt_tf32_kernel<<<(QKVC * DIMX / 4 + 255) / 256, 256>>>(Wqkv, wqkvc, QKVC * DIMX / 4);
    cvt_tf32_kernel<<<(DIMX * DIMX / 4 + 255) / 256, 256>>>(Wo,   woc,   DIMX * DIMX / 4);

    // 1) qkv = x @ Wqkv^T + bqkv, RoPE fused into epilogue
    gemm_mma_tf32<true><<<dim3(QKVC / GBN, T_TOK / GBM), 256, GEMM_SMEM>>>(
        xc, wqkvc, bqkv, qkv, QKVC, DIMX, cosT, sinT);
    // 2) sliding-window attention with sink (emits tf32-rounded attn)
    swa_kernel<<<dim3(T_TOK / TQ, NKV), 256, attn_smem>>>(sinks);
    // 3) out = attn @ Wo^T + bo
    gemm_mma_tf32<false><<<dim3(DIMX / GBN, T_TOK / GBM), 256, GEMM_SMEM>>>(
        att, woc, bo, out, DIMX, DIMX, nullptr, nullptr);
}

// round 10
// speedup vs baseline: 1.1782x; 1.1782x over previous
#include <cuda_runtime.h>
#include <math.h>
#include <cstdint>
#include <cstddef>

// ---------------- problem constants ----------------
#define T_TOK   2048
#define DIMX    2048
#define QKVC    3072      // (32 + 2*8) * 64
#define NKV     8
#define WIN     128
#define TQ      16

// Scratch (no allocs allowed)
__device__ float g_qkv[(size_t)T_TOK * QKVC];
__device__ float g_attn[(size_t)T_TOK * DIMX];
__device__ float g_xc[(size_t)T_TOK * DIMX];      // tf32-rounded x
__device__ float g_wqkvc[(size_t)QKVC * DIMX];    // tf32-rounded Wqkv
__device__ float g_woc[(size_t)DIMX * DIMX];      // tf32-rounded Wo

// ---------------- helpers ----------------
__device__ __forceinline__ uint32_t smem_u32(const void* p) {
    uint32_t a;
    asm("{ .reg .u64 t; cvta.to.shared.u64 t, %1; cvt.u32.u64 %0, t; }"
        : "=r"(a) : "l"(p));
    return a;
}
__device__ __forceinline__ float f2tf32f(float f) {
    uint32_t r;
    asm("cvt.rna.tf32.f32 %0, %1;" : "=r"(r) : "f"(f));
    return __uint_as_float(r);
}
__device__ __forceinline__ void mma_tf32(float* d, const uint32_t* a,
                                         const uint32_t* b) {
    asm volatile(
        "mma.sync.aligned.m16n8k8.row.col.f32.tf32.tf32.f32 "
        "{%0,%1,%2,%3}, {%4,%5,%6,%7}, {%8,%9}, {%0,%1,%2,%3};"
        : "+f"(d[0]), "+f"(d[1]), "+f"(d[2]), "+f"(d[3])
        : "r"(a[0]), "r"(a[1]), "r"(a[2]), "r"(a[3]), "r"(b[0]), "r"(b[1]));
}
__device__ __forceinline__ void ldsm_x4(uint32_t* r, uint32_t addr) {
    asm volatile(
        "ldmatrix.sync.aligned.m8n8.x4.shared.b16 {%0,%1,%2,%3}, [%4];"
        : "=r"(r[0]), "=r"(r[1]), "=r"(r[2]), "=r"(r[3]) : "r"(addr));
}

// ---------------- tf32 pre-round pass ----------------
__global__ void cvt_tf32_kernel(const float* __restrict__ in,
                                float* __restrict__ out, int n4)
{
    int i = blockIdx.x * blockDim.x + threadIdx.x;
    if (i < n4) {
        float4 v = *(const float4*)(in + (size_t)i * 4);
        v.x = f2tf32f(v.x); v.y = f2tf32f(v.y);
        v.z = f2tf32f(v.z); v.w = f2tf32f(v.w);
        *(float4*)(out + (size_t)i * 4) = v;
    }
}

// ---------------- tf32 mma.sync GEMM (R8 version, proven 466.9) -------------
#define GBM 128
#define GBN 128
#define GBK 32
#define PADW 36                    // 144B row stride; odd multiple of 16B
#define SSTG (GBM * PADW * 2)      // floats per stage (A + B) = 9216
#define GEMM_SMEM (3 * SSTG * 4)   // 110592 bytes

template <bool DO_ROPE>
__global__ __launch_bounds__(256, 2)     // force <=128 regs -> 2 CTAs/SM
void gemm_mma_tf32(const float* __restrict__ A, const float* __restrict__ B,
                   const float* __restrict__ bias, float* __restrict__ C,
                   int Ntot, int K,
                   const float* __restrict__ cosT, const float* __restrict__ sinT)
{
    extern __shared__ float smf[];
    const uint32_t sbase = smem_u32(smf);

    const int tid  = threadIdx.x;
    const int lane = tid & 31;
    const int wid  = tid >> 5;
    const int warpM = wid & 3;
    const int warpN = wid >> 2;
    const int gid = lane >> 2;
    const int tig = lane & 3;

    const int m0 = blockIdx.y * GBM;
    const int n0 = blockIdx.x * GBN;
    const int niter = K / GBK;

    const float* Ag = A + (size_t)m0 * K;
    const float* Bg = B + (size_t)n0 * K;

    const int r0 = tid >> 3;
    const int c4 = (tid & 7) * 4;

    const int q = lane >> 3;
    const int arow = ((q & 1) << 3) + (lane & 7);
    const int akof = (q >> 1) << 2;
    const int brow = ((q >> 1) << 3) + (lane & 7);
    const int bkof = (q & 1) << 2;
    const uint32_t a_off = (uint32_t)(((warpM * 32 + arow) * PADW + akof) * 4);
    const uint32_t b_off = (uint32_t)((GBM * PADW + (warpN * 64 + brow) * PADW + bkof) * 4);

    float acc[2][8][4];
#pragma unroll
    for (int mt = 0; mt < 2; mt++)
#pragma unroll
        for (int nt = 0; nt < 8; nt++)
#pragma unroll
            for (int z = 0; z < 4; z++) acc[mt][nt][z] = 0.f;

    auto issue = [&](int kt, int s) {
        if (kt < niter) {
            uint32_t abase = sbase + (uint32_t)(s * SSTG + r0 * PADW + c4) * 4;
            const float* ap = Ag + (size_t)r0 * K + kt * GBK + c4;
            const float* bp = Bg + (size_t)r0 * K + kt * GBK + c4;
            uint32_t bbase = abase + GBM * PADW * 4;
#pragma unroll
            for (int i = 0; i < 4; i++) {
                asm volatile("cp.async.cg.shared.global [%0], [%1], 16;"
                             :: "r"(abase + i * 32 * PADW * 4),
                                "l"(ap + (size_t)i * 32 * K) : "memory");
                asm volatile("cp.async.cg.shared.global [%0], [%1], 16;"
                             :: "r"(bbase + i * 32 * PADW * 4),
                                "l"(bp + (size_t)i * 32 * K) : "memory");
            }
        }
        asm volatile("cp.async.commit_group;" ::: "memory");
    };

    issue(0, 0);
    issue(1, 1);

    for (int it = 0; it < niter; it++) {
        asm volatile("cp.async.wait_group 1;" ::: "memory");
        __syncthreads();
        issue(it + 2, (it + 2) % 3);

        const uint32_t stg = sbase + (uint32_t)((it % 3) * SSTG) * 4;
        const uint32_t aB = stg + a_off;
        const uint32_t bB = stg + b_off;

#pragma unroll
        for (int ks = 0; ks < 4; ks++) {
            const uint32_t kb = ks * 32;
            uint32_t afr[2][4];
            ldsm_x4(afr[0], aB + kb);
            ldsm_x4(afr[1], aB + kb + 16 * PADW * 4);
            uint32_t bfr[4][4];
            ldsm_x4(bfr[0], bB + kb);
            ldsm_x4(bfr[1], bB + kb + 16 * PADW * 4);
            ldsm_x4(bfr[2], bB + kb + 32 * PADW * 4);
            ldsm_x4(bfr[3], bB + kb + 48 * PADW * 4);
#pragma unroll
            for (int mt = 0; mt < 2; mt++)
#pragma unroll
                for (int p = 0; p < 4; p++) {
                    mma_tf32(acc[mt][2 * p + 0], afr[mt], &bfr[p][0]);
                    mma_tf32(acc[mt][2 * p + 1], afr[mt], &bfr[p][2]);
                }
        }
    }

    const bool rope_tile = DO_ROPE && (n0 < 2560);
#pragma unroll
    for (int mt = 0; mt < 2; mt++) {
        int row = m0 + warpM * 32 + mt * 16 + gid;
#pragma unroll
        for (int np = 0; np < 4; np++) {
            int colL = n0 + warpN * 64 + np * 8 + 2 * tig;
            int colH = colL + 32;
            float L[4], H[4];
#pragma unroll
            for (int z = 0; z < 4; z++) {
                L[z] = acc[mt][np][z]     + __ldg(&bias[colL + (z & 1)]);
                H[z] = acc[mt][np + 4][z] + __ldg(&bias[colH + (z & 1)]);
            }
            if (rope_tile) {
                int dl = colL & 63;
                const float* c1 = cosT + (size_t)row * 64;
                const float* s1 = sinT + (size_t)row * 64;
                const float* c2 = c1 + 8 * 64;
                const float* s2 = s1 + 8 * 64;
#pragma unroll
                for (int z = 0; z < 4; z++) {
                    const float* cc = (z < 2) ? c1 : c2;
                    const float* ss = (z < 2) ? s1 : s2;
                    int d = dl + (z & 1);
                    float lo = L[z], hi = H[z];
                    L[z] = lo * cc[d]      - hi * ss[d];
                    H[z] = hi * cc[d + 32] + lo * ss[d + 32];
                }
            }
            *(float2*)(C + (size_t)row * Ntot + colL)       = make_float2(L[0], L[1]);
            *(float2*)(C + (size_t)(row + 8) * Ntot + colL) = make_float2(L[2], L[3]);
            *(float2*)(C + (size_t)row * Ntot + colH)       = make_float2(H[0], H[1]);
            *(float2*)(C + (size_t)(row + 8) * Ntot + colH) = make_float2(H[2], H[3]);
        }
    }
}

// ---------------- SWA v2: tensorized QK + PV in u-coordinates ----------------
// Per CTA: 16 query tokens x 1 kv head. Rows r = 4*i + g (64 rows).
// Keys u in [0,160): global key j = t0 - 127 + u; valid u <= 142 && j >= 0.
// S = Q[64x64] K[160x64]^T ; softmax banded; O = P[64x160] Vt[64x160]^T.
#define SQ_STR 68      // odd multiple of 16B -> LDSM conflict-free
#define SK_STR 68
#define SP_STR 164
#define SV_STR 164
#define NU     160
#define OFF_Q   0
#define OFF_K   4352                    // 64*68
#define OFF_V   15232                   // + 160*68
#define OFF_P   25728                   // + 64*164
#define OFF_DEN 36224                   // + 64*164
#define SWA_SMEM ((36224 + 64) * 4)     // 145152 bytes

__global__ __launch_bounds__(256, 1)
void swa_kernel(const float* __restrict__ sinks)
{
    extern __shared__ float sm[];
    const uint32_t sb = smem_u32(sm);
    const int tid = threadIdx.x, lane = tid & 31, wid = tid >> 5;
    const int gid = lane >> 2, tig = lane & 3;
    const int t0  = blockIdx.x * TQ;
    const int kvh = blockIdx.y;

    float* Qs  = sm + OFF_Q;
    float* Ks  = sm + OFF_K;
    float* Vt  = sm + OFF_V;
    float* P   = sm + OFF_P;
    float* den = sm + OFF_DEN;

    // ---- load K[u][d] and Vt[d][u] (rna-rounded, zero outside band) ----
    for (int idx = tid; idx < NU * 64; idx += 256) {
        int u = idx >> 6, d = idx & 63;
        int j = t0 - 127 + u;
        float kv = 0.f, vv = 0.f;
        if (u <= 142 && j >= 0) {
            const float* r = g_qkv + (size_t)j * QKVC;
            kv = f2tf32f(r[2048 + kvh * 64 + d]);
            vv = f2tf32f(r[2560 + kvh * 64 + d]);
        }
        Ks[u * SK_STR + d] = kv;
        Vt[d * SV_STR + u] = vv;
    }
    // ---- load Q (scaled, rounded) ----
    for (int idx = tid; idx < 64 * 64; idx += 256) {
        int r = idx >> 6, d = idx & 63;
        int i = r >> 2, g = r & 3;
        Qs[r * SQ_STR + d] = f2tf32f(
            g_qkv[(size_t)(t0 + i) * QKVC + (kvh * 4 + g) * 64 + d] * 0.125f);
    }
    __syncthreads();

    // ldmatrix per-lane constants (same scheme as GEMM, stride-independent)
    const int q = lane >> 3;
    const int arow = ((q & 1) << 3) + (lane & 7);
    const int akof = (q >> 1) << 2;
    const int brow = ((q >> 1) << 3) + (lane & 7);
    const int bkof = (q & 1) << 2;

    // ---- QK: warp grid 4M x 2N; warp tile 16 x 80 ----
    {
        const int mrow = (wid & 3) << 4;
        const int ncol = (wid >> 2) * 80;
        float s[10][4];
#pragma unroll
        for (int nt = 0; nt < 10; nt++)
#pragma unroll
            for (int z = 0; z < 4; z++) s[nt][z] = 0.f;

        const uint32_t Qb = sb + (uint32_t)((OFF_Q + (mrow + arow) * SQ_STR + akof) * 4);
        const uint32_t Kb = sb + (uint32_t)((OFF_K + (ncol + brow) * SK_STR + bkof) * 4);
#pragma unroll
        for (int ks = 0; ks < 8; ks++) {
            const uint32_t kb = ks * 32;
            uint32_t afr[4];
            ldsm_x4(afr, Qb + kb);
            uint32_t bfr[5][4];
#pragma unroll
            for (int p = 0; p < 5; p++)
                ldsm_x4(bfr[p], Kb + kb + (uint32_t)(p * 16 * SK_STR * 4));
#pragma unroll
            for (int p = 0; p < 5; p++) {
                mma_tf32(s[2 * p + 0], afr, &bfr[p][0]);
                mma_tf32(s[2 * p + 1], afr, &bfr[p][2]);
            }
        }
#pragma unroll
        for (int nt = 0; nt < 10; nt++) {
            int col = ncol + nt * 8 + 2 * tig;
            P[(mrow + gid) * SP_STR + col]         = s[nt][0];
            P[(mrow + gid) * SP_STR + col + 1]     = s[nt][1];
            P[(mrow + gid + 8) * SP_STR + col]     = s[nt][2];
            P[(mrow + gid + 8) * SP_STR + col + 1] = s[nt][3];
        }
    }
    __syncthreads();

    // ---- banded softmax (warp per 8 rows) ----
    {
        const int lim = 127 - t0;
        for (int rr = 0; rr < 8; rr++) {
            int r = wid * 8 + rr;
            int i = r >> 2, g = r & 3;
            int lo = (i > lim) ? i : lim;
            int hi = i + 127;
            float v[5];
#pragma unroll
            for (int c = 0; c < 5; c++) {
                int u = lane + c * 32;
                float x = P[r * SP_STR + u];
                v[c] = (u >= lo && u <= hi) ? x : -1e30f;
            }
            float m = v[0];
#pragma unroll
            for (int c = 1; c < 5; c++) m = fmaxf(m, v[c]);
#pragma unroll
            for (int o = 16; o; o >>= 1)
                m = fmaxf(m, __shfl_xor_sync(0xffffffffu, m, o));
            float snk = __ldg(&sinks[kvh * 4 + g]);
            m = fmaxf(m, snk);
            float sum = 0.f;
#pragma unroll
            for (int c = 0; c < 5; c++) {
                int u = lane + c * 32;
                float e = 0.f;
                if (u >= lo && u <= hi) e = f2tf32f(__expf(v[c] - m));
                P[r * SP_STR + u] = e;
                sum += e;
            }
#pragma unroll
            for (int o = 16; o; o >>= 1)
                sum += __shfl_xor_sync(0xffffffffu, sum, o);
            sum += __expf(snk - m);
            if (lane == 0) den[r] = 1.0f / sum;
        }
    }
    __syncthreads();

    // ---- PV: warp grid 4M x 2N; warp tile 16 x 32; K = 160 ----
    {
        const int mrow = (wid & 3) << 4;
        const int ncol = (wid >> 2) << 5;
        float o[4][4];
#pragma unroll
        for (int nt = 0; nt < 4; nt++)
#pragma unroll
            for (int z = 0; z < 4; z++) o[nt][z] = 0.f;

        const uint32_t Pb = sb + (uint32_t)((OFF_P + (mrow + arow) * SP_STR + akof) * 4);
        const uint32_t Vb = sb + (uint32_t)((OFF_V + (ncol + brow) * SV_STR + bkof) * 4);
#pragma unroll
        for (int ks = 0; ks < 20; ks++) {
            const uint32_t kb = ks * 32;
            uint32_t afr[4];
            ldsm_x4(afr, Pb + kb);
            uint32_t bfr[2][4];
            ldsm_x4(bfr[0], Vb + kb);
            ldsm_x4(bfr[1], Vb + kb + (uint32_t)(16 * SV_STR * 4));
#pragma unroll
            for (int p = 0; p < 2; p++) {
                mma_tf32(o[2 * p + 0], afr, &bfr[p][0]);
                mma_tf32(o[2 * p + 1], afr, &bfr[p][2]);
            }
        }
        int r0 = mrow + gid, r1 = r0 + 8;
        float i0 = den[r0], i1 = den[r1];
        int tA = t0 + (r0 >> 2), chA = (kvh * 4 + (r0 & 3)) * 64;
        int tB = t0 + (r1 >> 2), chB = (kvh * 4 + (r1 & 3)) * 64;
#pragma unroll
        for (int nt = 0; nt < 4; nt++) {
            int col = ncol + nt * 8 + 2 * tig;
            g_attn[(size_t)tA * DIMX + chA + col]     = f2tf32f(o[nt][0] * i0);
            g_attn[(size_t)tA * DIMX + chA + col + 1] = f2tf32f(o[nt][1] * i0);
            g_attn[(size_t)tB * DIMX + chB + col]     = f2tf32f(o[nt][2] * i1);
            g_attn[(size_t)tB * DIMX + chB + col + 1] = f2tf32f(o[nt][3] * i1);
        }
    }
}

// ---------------- host ----------------
extern "C" void kernel_launch(void* const* d_in, const int* in_sizes, int n_in,
                              void* d_out, int out_size)
{
    (void)in_sizes; (void)n_in; (void)out_size;
    const float* x     = (const float*)d_in[0];
    const float* cosT  = (const float*)d_in[1];
    const float* sinT  = (const float*)d_in[2];
    const float* Wqkv  = (const float*)d_in[3];
    const float* bqkv  = (const float*)d_in[4];
    const float* Wo    = (const float*)d_in[5];
    const float* bo    = (const float*)d_in[6];
    const float* sinks = (const float*)d_in[7];
    float* out = (float*)d_out;

    float *qkv = nullptr, *att = nullptr;
    float *xc = nullptr, *wqkvc = nullptr, *woc = nullptr;
    cudaGetSymbolAddress((void**)&qkv,   g_qkv);
    cudaGetSymbolAddress((void**)&att,   g_attn);
    cudaGetSymbolAddress((void**)&xc,    g_xc);
    cudaGetSymbolAddress((void**)&wqkvc, g_wqkvc);
    cudaGetSymbolAddress((void**)&woc,   g_woc);

    cudaFuncSetAttribute(gemm_mma_tf32<true>,
                         cudaFuncAttributeMaxDynamicSharedMemorySize, GEMM_SMEM);
    cudaFuncSetAttribute(gemm_mma_tf32<false>,
                         cudaFuncAttributeMaxDynamicSharedMemorySize, GEMM_SMEM);
    cudaFuncSetAttribute(swa_kernel,
                         cudaFuncAttributeMaxDynamicSharedMemorySize, SWA_SMEM);

    // 0) tf32 pre-rounding passes
    cvt_tf32_kernel<<<(T_TOK * DIMX / 4 + 255) / 256, 256>>>(x,    xc,    T_TOK * DIMX / 4);
    cvt_tf32_kernel<<<(QKVC * DIMX / 4 + 255) / 256, 256>>>(Wqkv, wqkvc, QKVC * DIMX / 4);
    cvt_tf32_kernel<<<(DIMX * DIMX / 4 + 255) / 256, 256>>>(Wo,   woc,   DIMX * DIMX / 4);

    // 1) qkv = x @ Wqkv^T + bqkv, RoPE fused into epilogue
    gemm_mma_tf32<true><<<dim3(QKVC / GBN, T_TOK / GBM), 256, GEMM_SMEM>>>(
        xc, wqkvc, bqkv, qkv, QKVC, DIMX, cosT, sinT);
    // 2) tensorized sliding-window attention with sink
    swa_kernel<<<dim3(T_TOK / TQ, NKV), 256, SWA_SMEM>>>(sinks);
    // 3) out = attn @ Wo^T + bo
    gemm_mma_tf32<false><<<dim3(DIMX / GBN, T_TOK / GBM), 256, GEMM_SMEM>>>(
        att, woc, bo, out, DIMX, DIMX, nullptr, nullptr);
}

// round 11
// speedup vs baseline: 1.2935x; 1.0978x over previous
#include <cuda_runtime.h>
#include <math.h>
#include <cstdint>
#include <cstddef>

// ---------------- problem constants ----------------
#define T_TOK   2048
#define DIMX    2048
#define QKVC    3072      // (32 + 2*8) * 64
#define NKV     8
#define WIN     128
#define TQ      16

// Scratch (no allocs allowed)
__device__ float g_qkv[(size_t)T_TOK * QKVC];
__device__ float g_attn[(size_t)T_TOK * DIMX];
__device__ float g_xc[(size_t)T_TOK * DIMX];      // tf32-rounded x
__device__ float g_wqkvc[(size_t)QKVC * DIMX];    // tf32-rounded Wqkv
__device__ float g_woc[(size_t)DIMX * DIMX];      // tf32-rounded Wo

// ---------------- helpers ----------------
__device__ __forceinline__ uint32_t smem_u32(const void* p) {
    uint32_t a;
    asm("{ .reg .u64 t; cvta.to.shared.u64 t, %1; cvt.u32.u64 %0, t; }"
        : "=r"(a) : "l"(p));
    return a;
}
__device__ __forceinline__ float f2tf32f(float f) {
    uint32_t r;
    asm("cvt.rna.tf32.f32 %0, %1;" : "=r"(r) : "f"(f));
    return __uint_as_float(r);
}
__device__ __forceinline__ void mma_tf32(float* d, const uint32_t* a,
                                         const uint32_t* b) {
    asm volatile(
        "mma.sync.aligned.m16n8k8.row.col.f32.tf32.tf32.f32 "
        "{%0,%1,%2,%3}, {%4,%5,%6,%7}, {%8,%9}, {%0,%1,%2,%3};"
        : "+f"(d[0]), "+f"(d[1]), "+f"(d[2]), "+f"(d[3])
        : "r"(a[0]), "r"(a[1]), "r"(a[2]), "r"(a[3]), "r"(b[0]), "r"(b[1]));
}
__device__ __forceinline__ void ldsm_x4(uint32_t* r, uint32_t addr) {
    asm volatile(
        "ldmatrix.sync.aligned.m8n8.x4.shared.b16 {%0,%1,%2,%3}, [%4];"
        : "=r"(r[0]), "=r"(r[1]), "=r"(r[2]), "=r"(r[3]) : "r"(addr));
}

// ---------------- tf32 pre-round pass ----------------
__global__ void cvt_tf32_kernel(const float* __restrict__ in,
                                float* __restrict__ out, int n4)
{
    int i = blockIdx.x * blockDim.x + threadIdx.x;
    if (i < n4) {
        float4 v = *(const float4*)(in + (size_t)i * 4);
        v.x = f2tf32f(v.x); v.y = f2tf32f(v.y);
        v.z = f2tf32f(v.z); v.w = f2tf32f(v.w);
        *(float4*)(out + (size_t)i * 4) = v;
    }
}

// ---------------- tf32 mma.sync GEMM (R8 version, frozen) -------------------
#define GBM 128
#define GBN 128
#define GBK 32
#define PADW 36                    // 144B row stride; odd multiple of 16B
#define SSTG (GBM * PADW * 2)      // floats per stage (A + B) = 9216
#define GEMM_SMEM (3 * SSTG * 4)   // 110592 bytes

template <bool DO_ROPE>
__global__ __launch_bounds__(256, 2)     // force <=128 regs -> 2 CTAs/SM
void gemm_mma_tf32(const float* __restrict__ A, const float* __restrict__ B,
                   const float* __restrict__ bias, float* __restrict__ C,
                   int Ntot, int K,
                   const float* __restrict__ cosT, const float* __restrict__ sinT)
{
    extern __shared__ float smf[];
    const uint32_t sbase = smem_u32(smf);

    const int tid  = threadIdx.x;
    const int lane = tid & 31;
    const int wid  = tid >> 5;
    const int warpM = wid & 3;
    const int warpN = wid >> 2;
    const int gid = lane >> 2;
    const int tig = lane & 3;

    const int m0 = blockIdx.y * GBM;
    const int n0 = blockIdx.x * GBN;
    const int niter = K / GBK;

    const float* Ag = A + (size_t)m0 * K;
    const float* Bg = B + (size_t)n0 * K;

    const int r0 = tid >> 3;
    const int c4 = (tid & 7) * 4;

    const int q = lane >> 3;
    const int arow = ((q & 1) << 3) + (lane & 7);
    const int akof = (q >> 1) << 2;
    const int brow = ((q >> 1) << 3) + (lane & 7);
    const int bkof = (q & 1) << 2;
    const uint32_t a_off = (uint32_t)(((warpM * 32 + arow) * PADW + akof) * 4);
    const uint32_t b_off = (uint32_t)((GBM * PADW + (warpN * 64 + brow) * PADW + bkof) * 4);

    float acc[2][8][4];
#pragma unroll
    for (int mt = 0; mt < 2; mt++)
#pragma unroll
        for (int nt = 0; nt < 8; nt++)
#pragma unroll
            for (int z = 0; z < 4; z++) acc[mt][nt][z] = 0.f;

    auto issue = [&](int kt, int s) {
        if (kt < niter) {
            uint32_t abase = sbase + (uint32_t)(s * SSTG + r0 * PADW + c4) * 4;
            const float* ap = Ag + (size_t)r0 * K + kt * GBK + c4;
            const float* bp = Bg + (size_t)r0 * K + kt * GBK + c4;
            uint32_t bbase = abase + GBM * PADW * 4;
#pragma unroll
            for (int i = 0; i < 4; i++) {
                asm volatile("cp.async.cg.shared.global [%0], [%1], 16;"
                             :: "r"(abase + i * 32 * PADW * 4),
                                "l"(ap + (size_t)i * 32 * K) : "memory");
                asm volatile("cp.async.cg.shared.global [%0], [%1], 16;"
                             :: "r"(bbase + i * 32 * PADW * 4),
                                "l"(bp + (size_t)i * 32 * K) : "memory");
            }
        }
        asm volatile("cp.async.commit_group;" ::: "memory");
    };

    issue(0, 0);
    issue(1, 1);

    for (int it = 0; it < niter; it++) {
        asm volatile("cp.async.wait_group 1;" ::: "memory");
        __syncthreads();
        issue(it + 2, (it + 2) % 3);

        const uint32_t stg = sbase + (uint32_t)((it % 3) * SSTG) * 4;
        const uint32_t aB = stg + a_off;
        const uint32_t bB = stg + b_off;

#pragma unroll
        for (int ks = 0; ks < 4; ks++) {
            const uint32_t kb = ks * 32;
            uint32_t afr[2][4];
            ldsm_x4(afr[0], aB + kb);
            ldsm_x4(afr[1], aB + kb + 16 * PADW * 4);
            uint32_t bfr[4][4];
            ldsm_x4(bfr[0], bB + kb);
            ldsm_x4(bfr[1], bB + kb + 16 * PADW * 4);
            ldsm_x4(bfr[2], bB + kb + 32 * PADW * 4);
            ldsm_x4(bfr[3], bB + kb + 48 * PADW * 4);
#pragma unroll
            for (int mt = 0; mt < 2; mt++)
#pragma unroll
                for (int p = 0; p < 4; p++) {
                    mma_tf32(acc[mt][2 * p + 0], afr[mt], &bfr[p][0]);
                    mma_tf32(acc[mt][2 * p + 1], afr[mt], &bfr[p][2]);
                }
        }
    }

    const bool rope_tile = DO_ROPE && (n0 < 2560);
#pragma unroll
    for (int mt = 0; mt < 2; mt++) {
        int row = m0 + warpM * 32 + mt * 16 + gid;
#pragma unroll
        for (int np = 0; np < 4; np++) {
            int colL = n0 + warpN * 64 + np * 8 + 2 * tig;
            int colH = colL + 32;
            float L[4], H[4];
#pragma unroll
            for (int z = 0; z < 4; z++) {
                L[z] = acc[mt][np][z]     + __ldg(&bias[colL + (z & 1)]);
                H[z] = acc[mt][np + 4][z] + __ldg(&bias[colH + (z & 1)]);
            }
            if (rope_tile) {
                int dl = colL & 63;
                const float* c1 = cosT + (size_t)row * 64;
                const float* s1 = sinT + (size_t)row * 64;
                const float* c2 = c1 + 8 * 64;
                const float* s2 = s1 + 8 * 64;
#pragma unroll
                for (int z = 0; z < 4; z++) {
                    const float* cc = (z < 2) ? c1 : c2;
                    const float* ss = (z < 2) ? s1 : s2;
                    int d = dl + (z & 1);
                    float lo = L[z], hi = H[z];
                    L[z] = lo * cc[d]      - hi * ss[d];
                    H[z] = hi * cc[d + 32] + lo * ss[d + 32];
                }
            }
            *(float2*)(C + (size_t)row * Ntot + colL)       = make_float2(L[0], L[1]);
            *(float2*)(C + (size_t)(row + 8) * Ntot + colL) = make_float2(L[2], L[3]);
            *(float2*)(C + (size_t)row * Ntot + colH)       = make_float2(H[0], H[1]);
            *(float2*)(C + (size_t)(row + 8) * Ntot + colH) = make_float2(H[2], H[3]);
        }
    }
}

// ---------------- SWA v3: tensorized, P aliased onto K -> 2 CTAs/SM ---------
// Per CTA: 16 query tokens x 1 kv head. Rows r = 4*i + g (64 rows).
// Keys u in [0,160): global key j = t0 - 127 + u; valid u <= 142 && j >= 0.
// S = Q K^T (into regs) -> barrier -> P overwrites K -> softmax -> PV.
#define SQ_STR 68      // odd multiple of 16B -> LDSM conflict-free
#define SK_STR 68
#define SP_STR 164
#define SV_STR 164
#define NU     160
#define OFF_Q   0
#define OFF_K   4352                    // 64*68
#define OFF_P   OFF_K                   // P (64*164=10496) aliases K (160*68=10880)
#define OFF_V   15232                   // OFF_K + 160*68
#define OFF_DEN 25728                   // OFF_V + 64*164
#define SWA_SMEM ((25728 + 64) * 4)     // 103168 bytes -> 2 CTAs/SM

__global__ __launch_bounds__(256, 2)
void swa_kernel(const float* __restrict__ sinks)
{
    extern __shared__ float sm[];
    const uint32_t sb = smem_u32(sm);
    const int tid = threadIdx.x, lane = tid & 31, wid = tid >> 5;
    const int gid = lane >> 2, tig = lane & 3;
    const int t0  = blockIdx.x * TQ;
    const int kvh = blockIdx.y;

    float* Qs  = sm + OFF_Q;
    float* Ks  = sm + OFF_K;
    float* Vt  = sm + OFF_V;
    float* P   = sm + OFF_P;
    float* den = sm + OFF_DEN;

    // ---- load K[u][d] and Vt[d][u] (rna-rounded, zero outside band) ----
    for (int idx = tid; idx < NU * 64; idx += 256) {
        int u = idx >> 6, d = idx & 63;
        int j = t0 - 127 + u;
        float kv = 0.f, vv = 0.f;
        if (u <= 142 && j >= 0) {
            const float* r = g_qkv + (size_t)j * QKVC;
            kv = f2tf32f(r[2048 + kvh * 64 + d]);
            vv = f2tf32f(r[2560 + kvh * 64 + d]);
        }
        Ks[u * SK_STR + d] = kv;
        Vt[d * SV_STR + u] = vv;
    }
    // ---- load Q (scaled, rounded) ----
    for (int idx = tid; idx < 64 * 64; idx += 256) {
        int r = idx >> 6, d = idx & 63;
        int i = r >> 2, g = r & 3;
        Qs[r * SQ_STR + d] = f2tf32f(
            g_qkv[(size_t)(t0 + i) * QKVC + (kvh * 4 + g) * 64 + d] * 0.125f);
    }
    __syncthreads();

    // ldmatrix per-lane constants
    const int q = lane >> 3;
    const int arow = ((q & 1) << 3) + (lane & 7);
    const int akof = (q >> 1) << 2;
    const int brow = ((q >> 1) << 3) + (lane & 7);
    const int bkof = (q & 1) << 2;

    // ---- QK: warp grid 4M x 2N; warp tile 16 x 80; scores stay in regs ----
    {
        const int mrow = (wid & 3) << 4;
        const int ncol = (wid >> 2) * 80;
        float s[10][4];
#pragma unroll
        for (int nt = 0; nt < 10; nt++)
#pragma unroll
            for (int z = 0; z < 4; z++) s[nt][z] = 0.f;

        const uint32_t Qb = sb + (uint32_t)((OFF_Q + (mrow + arow) * SQ_STR + akof) * 4);
        const uint32_t Kb = sb + (uint32_t)((OFF_K + (ncol + brow) * SK_STR + bkof) * 4);
#pragma unroll
        for (int ks = 0; ks < 8; ks++) {
            const uint32_t kb = ks * 32;
            uint32_t afr[4];
            ldsm_x4(afr, Qb + kb);
            uint32_t bfr[5][4];
#pragma unroll
            for (int p = 0; p < 5; p++)
                ldsm_x4(bfr[p], Kb + kb + (uint32_t)(p * 16 * SK_STR * 4));
#pragma unroll
            for (int p = 0; p < 5; p++) {
                mma_tf32(s[2 * p + 0], afr, &bfr[p][0]);
                mma_tf32(s[2 * p + 1], afr, &bfr[p][2]);
            }
        }
        // all warps must finish READING K before P overwrites it
        __syncthreads();
#pragma unroll
        for (int nt = 0; nt < 10; nt++) {
            int col = ncol + nt * 8 + 2 * tig;
            P[(mrow + gid) * SP_STR + col]         = s[nt][0];
            P[(mrow + gid) * SP_STR + col + 1]     = s[nt][1];
            P[(mrow + gid + 8) * SP_STR + col]     = s[nt][2];
            P[(mrow + gid + 8) * SP_STR + col + 1] = s[nt][3];
        }
    }
    __syncthreads();

    // ---- banded softmax (warp per 8 rows) ----
    {
        const int lim = 127 - t0;
        for (int rr = 0; rr < 8; rr++) {
            int r = wid * 8 + rr;
            int i = r >> 2, g = r & 3;
            int lo = (i > lim) ? i : lim;
            int hi = i + 127;
            float v[5];
#pragma unroll
            for (int c = 0; c < 5; c++) {
                int u = lane + c * 32;
                float x = P[r * SP_STR + u];
                v[c] = (u >= lo && u <= hi) ? x : -1e30f;
            }
            float m = v[0];
#pragma unroll
            for (int c = 1; c < 5; c++) m = fmaxf(m, v[c]);
#pragma unroll
            for (int o = 16; o; o >>= 1)
                m = fmaxf(m, __shfl_xor_sync(0xffffffffu, m, o));
            float snk = __ldg(&sinks[kvh * 4 + g]);
            m = fmaxf(m, snk);
            float sum = 0.f;
#pragma unroll
            for (int c = 0; c < 5; c++) {
                int u = lane + c * 32;
                float e = 0.f;
                if (u >= lo && u <= hi) e = f2tf32f(__expf(v[c] - m));
                P[r * SP_STR + u] = e;
                sum += e;
            }
#pragma unroll
            for (int o = 16; o; o >>= 1)
                sum += __shfl_xor_sync(0xffffffffu, sum, o);
            sum += __expf(snk - m);
            if (lane == 0) den[r] = 1.0f / sum;
        }
    }
    __syncthreads();

    // ---- PV: warp grid 4M x 2N; warp tile 16 x 32; K = 160 ----
    {
        const int mrow = (wid & 3) << 4;
        const int ncol = (wid >> 2) << 5;
        float o[4][4];
#pragma unroll
        for (int nt = 0; nt < 4; nt++)
#pragma unroll
            for (int z = 0; z < 4; z++) o[nt][z] = 0.f;

        const uint32_t Pb = sb + (uint32_t)((OFF_P + (mrow + arow) * SP_STR + akof) * 4);
        const uint32_t Vb = sb + (uint32_t)((OFF_V + (ncol + brow) * SV_STR + bkof) * 4);
#pragma unroll
        for (int ks = 0; ks < 20; ks++) {
            const uint32_t kb = ks * 32;
            uint32_t afr[4];
            ldsm_x4(afr, Pb + kb);
            uint32_t bfr[2][4];
            ldsm_x4(bfr[0], Vb + kb);
            ldsm_x4(bfr[1], Vb + kb + (uint32_t)(16 * SV_STR * 4));
#pragma unroll
            for (int p = 0; p < 2; p++) {
                mma_tf32(o[2 * p + 0], afr, &bfr[p][0]);
                mma_tf32(o[2 * p + 1], afr, &bfr[p][2]);
            }
        }
        int r0 = mrow + gid, r1 = r0 + 8;
        float i0 = den[r0], i1 = den[r1];
        int tA = t0 + (r0 >> 2), chA = (kvh * 4 + (r0 & 3)) * 64;
        int tB = t0 + (r1 >> 2), chB = (kvh * 4 + (r1 & 3)) * 64;
#pragma unroll
        for (int nt = 0; nt < 4; nt++) {
            int col = ncol + nt * 8 + 2 * tig;
            g_attn[(size_t)tA * DIMX + chA + col]     = f2tf32f(o[nt][0] * i0);
            g_attn[(size_t)tA * DIMX + chA + col + 1] = f2tf32f(o[nt][1] * i0);
            g_attn[(size_t)tB * DIMX + chB + col]     = f2tf32f(o[nt][2] * i1);
            g_attn[(size_t)tB * DIMX + chB + col + 1] = f2tf32f(o[nt][3] * i1);
        }
    }
}

// ---------------- host ----------------
extern "C" void kernel_launch(void* const* d_in, const int* in_sizes, int n_in,
                              void* d_out, int out_size)
{
    (void)in_sizes; (void)n_in; (void)out_size;
    const float* x     = (const float*)d_in[0];
    const float* cosT  = (const float*)d_in[1];
    const float* sinT  = (const float*)d_in[2];
    const float* Wqkv  = (const float*)d_in[3];
    const float* bqkv  = (const float*)d_in[4];
    const float* Wo    = (const float*)d_in[5];
    const float* bo    = (const float*)d_in[6];
    const float* sinks = (const float*)d_in[7];
    float* out = (float*)d_out;

    float *qkv = nullptr, *att = nullptr;
    float *xc = nullptr, *wqkvc = nullptr, *woc = nullptr;
    cudaGetSymbolAddress((void**)&qkv,   g_qkv);
    cudaGetSymbolAddress((void**)&att,   g_attn);
    cudaGetSymbolAddress((void**)&xc,    g_xc);
    cudaGetSymbolAddress((void**)&wqkvc, g_wqkvc);
    cudaGetSymbolAddress((void**)&woc,   g_woc);

    cudaFuncSetAttribute(gemm_mma_tf32<true>,
                         cudaFuncAttributeMaxDynamicSharedMemorySize, GEMM_SMEM);
    cudaFuncSetAttribute(gemm_mma_tf32<false>,
                         cudaFuncAttributeMaxDynamicSharedMemorySize, GEMM_SMEM);
    cudaFuncSetAttribute(swa_kernel,
                         cudaFuncAttributeMaxDynamicSharedMemorySize, SWA_SMEM);

    // 0) tf32 pre-rounding passes
    cvt_tf32_kernel<<<(T_TOK * DIMX / 4 + 255) / 256, 256>>>(x,    xc,    T_TOK * DIMX / 4);
    cvt_tf32_kernel<<<(QKVC * DIMX / 4 + 255) / 256, 256>>>(Wqkv, wqkvc, QKVC * DIMX / 4);
    cvt_tf32_kernel<<<(DIMX * DIMX / 4 + 255) / 256, 256>>>(Wo,   woc,   DIMX * DIMX / 4);

    // 1) qkv = x @ Wqkv^T + bqkv, RoPE fused into epilogue
    gemm_mma_tf32<true><<<dim3(QKVC / GBN, T_TOK / GBM), 256, GEMM_SMEM>>>(
        xc, wqkvc, bqkv, qkv, QKVC, DIMX, cosT, sinT);
    // 2) tensorized sliding-window attention with sink (2 CTAs/SM)
    swa_kernel<<<dim3(T_TOK / TQ, NKV), 256, SWA_SMEM>>>(sinks);
    // 3) out = attn @ Wo^T + bo
    gemm_mma_tf32<false><<<dim3(DIMX / GBN, T_TOK / GBM), 256, GEMM_SMEM>>>(
        att, woc, bo, out, DIMX, DIMX, nullptr, nullptr);
}

// round 13
// speedup vs baseline: 1.3065x; 1.0101x over previous
#include <cuda_runtime.h>
#include <math.h>
#include <cstdint>
#include <cstddef>

// ---------------- problem constants ----------------
#define T_TOK   2048
#define DIMX    2048
#define QKVC    3072      // (32 + 2*8) * 64
#define NKV     8
#define WIN     128
#define TQ      16

// Scratch (no allocs allowed)
__device__ float g_qkv[(size_t)T_TOK * QKVC];
__device__ float g_attn[(size_t)T_TOK * DIMX];
__device__ float g_xc[(size_t)T_TOK * DIMX];      // tf32-rounded x
__device__ float g_wqkvc[(size_t)QKVC * DIMX];    // tf32-rounded Wqkv
__device__ float g_woc[(size_t)DIMX * DIMX];      // tf32-rounded Wo

// ---------------- helpers ----------------
__device__ __forceinline__ uint32_t smem_u32(const void* p) {
    uint32_t a;
    asm("{ .reg .u64 t; cvta.to.shared.u64 t, %1; cvt.u32.u64 %0, t; }"
        : "=r"(a) : "l"(p));
    return a;
}
__device__ __forceinline__ float f2tf32f(float f) {
    uint32_t r;
    asm("cvt.rna.tf32.f32 %0, %1;" : "=r"(r) : "f"(f));
    return __uint_as_float(r);
}
__device__ __forceinline__ void mma_tf32(float* d, const uint32_t* a,
                                         const uint32_t* b) {
    asm volatile(
        "mma.sync.aligned.m16n8k8.row.col.f32.tf32.tf32.f32 "
        "{%0,%1,%2,%3}, {%4,%5,%6,%7}, {%8,%9}, {%0,%1,%2,%3};"
        : "+f"(d[0]), "+f"(d[1]), "+f"(d[2]), "+f"(d[3])
        : "r"(a[0]), "r"(a[1]), "r"(a[2]), "r"(a[3]), "r"(b[0]), "r"(b[1]));
}
__device__ __forceinline__ void ldsm_x4(uint32_t* r, uint32_t addr) {
    asm volatile(
        "ldmatrix.sync.aligned.m8n8.x4.shared.b16 {%0,%1,%2,%3}, [%4];"
        : "=r"(r[0]), "=r"(r[1]), "=r"(r[2]), "=r"(r[3]) : "r"(addr));
}

// ---------------- tf32 pre-round pass ----------------
__global__ void cvt_tf32_kernel(const float* __restrict__ in,
                                float* __restrict__ out, int n4)
{
    int i = blockIdx.x * blockDim.x + threadIdx.x;
    if (i < n4) {
        float4 v = *(const float4*)(in + (size_t)i * 4);
        v.x = f2tf32f(v.x); v.y = f2tf32f(v.y);
        v.z = f2tf32f(v.z); v.w = f2tf32f(v.w);
        *(float4*)(out + (size_t)i * 4) = v;
    }
}

// ---------------- tf32 mma.sync GEMM, templated on N-tile -------------------
// C[M, Ntot] = A[M, K] * B[Ntot, K]^T + bias.  Inputs MUST be tf32-pre-rounded.
// CTA tile 128 x (16*NT), BK=32, 3-stage cp.async pipeline, 256 threads,
// warp grid 4M x 2N (warp tile 32 x 8*NT). NT=8 -> BN=128; NT=6 -> BN=96.
#define GBM  128
#define GBK  32
#define PADW 36                    // 144B row stride; odd multiple of 16B

template <int NT>
__global__ __launch_bounds__(256, 2)     // force <=128 regs -> 2 CTAs/SM
void gemm_mma_tf32(const float* __restrict__ A, const float* __restrict__ B,
                   const float* __restrict__ bias, float* __restrict__ C,
                   int Ntot, int K)
{
    constexpr int BN   = NT * 16;            // CTA N-tile
    constexpr int SSTG = (GBM + BN) * PADW;  // floats per stage

    extern __shared__ float smf[];
    const uint32_t sbase = smem_u32(smf);

    const int tid  = threadIdx.x;
    const int lane = tid & 31;
    const int wid  = tid >> 5;
    const int warpM = wid & 3;
    const int warpN = wid >> 2;
    const int gid = lane >> 2;
    const int tig = lane & 3;

    const int m0 = blockIdx.y * GBM;
    const int n0 = blockIdx.x * BN;
    const int niter = K / GBK;

    const float* Ag = A + (size_t)m0 * K;
    const float* Bg = B + (size_t)n0 * K;

    const int r0 = tid >> 3;
    const int c4 = (tid & 7) * 4;

    const int q = lane >> 3;
    const int arow = ((q & 1) << 3) + (lane & 7);
    const int akof = (q >> 1) << 2;
    const int brow = ((q >> 1) << 3) + (lane & 7);
    const int bkof = (q & 1) << 2;
    const uint32_t a_off = (uint32_t)(((warpM * 32 + arow) * PADW + akof) * 4);
    const uint32_t b_off = (uint32_t)((GBM * PADW + (warpN * NT * 8 + brow) * PADW + bkof) * 4);

    float acc[2][NT][4];
#pragma unroll
    for (int mt = 0; mt < 2; mt++)
#pragma unroll
        for (int nt = 0; nt < NT; nt++)
#pragma unroll
            for (int z = 0; z < 4; z++) acc[mt][nt][z] = 0.f;

    auto issue = [&](int kt, int s) {
        if (kt < niter) {
            uint32_t abase = sbase + (uint32_t)(s * SSTG + r0 * PADW + c4) * 4;
            const float* ap = Ag + (size_t)r0 * K + kt * GBK + c4;
            const float* bp = Bg + (size_t)r0 * K + kt * GBK + c4;
            uint32_t bbase = abase + GBM * PADW * 4;
#pragma unroll
            for (int i = 0; i < 4; i++)
                asm volatile("cp.async.cg.shared.global [%0], [%1], 16;"
                             :: "r"(abase + i * 32 * PADW * 4),
                                "l"(ap + (size_t)i * 32 * K) : "memory");
#pragma unroll
            for (int i = 0; i < BN / 32; i++)
                asm volatile("cp.async.cg.shared.global [%0], [%1], 16;"
                             :: "r"(bbase + i * 32 * PADW * 4),
                                "l"(bp + (size_t)i * 32 * K) : "memory");
        }
        asm volatile("cp.async.commit_group;" ::: "memory");
    };

    issue(0, 0);
    issue(1, 1);

    for (int it = 0; it < niter; it++) {
        asm volatile("cp.async.wait_group 1;" ::: "memory");
        __syncthreads();
        issue(it + 2, (it + 2) % 3);

        const uint32_t stg = sbase + (uint32_t)((it % 3) * SSTG) * 4;
        const uint32_t aB = stg + a_off;
        const uint32_t bB = stg + b_off;

#pragma unroll
        for (int ks = 0; ks < 4; ks++) {
            const uint32_t kb = ks * 32;
            uint32_t afr[2][4];
            ldsm_x4(afr[0], aB + kb);
            ldsm_x4(afr[1], aB + kb + 16 * PADW * 4);
            uint32_t bfr[NT / 2][4];
#pragma unroll
            for (int p = 0; p < NT / 2; p++)
                ldsm_x4(bfr[p], bB + kb + (uint32_t)(p * 16 * PADW * 4));
#pragma unroll
            for (int mt = 0; mt < 2; mt++)
#pragma unroll
                for (int p = 0; p < NT / 2; p++) {
                    mma_tf32(acc[mt][2 * p + 0], afr[mt], &bfr[p][0]);
                    mma_tf32(acc[mt][2 * p + 1], afr[mt], &bfr[p][2]);
                }
        }
    }

    // ---- epilogue: bias only ----
#pragma unroll
    for (int mt = 0; mt < 2; mt++) {
        int row = m0 + warpM * 32 + mt * 16 + gid;
#pragma unroll
        for (int nt = 0; nt < NT; nt++) {
            int col = n0 + warpN * NT * 8 + nt * 8 + 2 * tig;
            float b0 = __ldg(&bias[col]);
            float b1 = __ldg(&bias[col + 1]);
            *(float2*)(C + (size_t)row * Ntot + col) =
                make_float2(acc[mt][nt][0] + b0, acc[mt][nt][1] + b1);
            *(float2*)(C + (size_t)(row + 8) * Ntot + col) =
                make_float2(acc[mt][nt][2] + b0, acc[mt][nt][3] + b1);
        }
    }
}

#define GEMM_SMEM_NT6 ((GBM + 96)  * PADW * 4 * 3)   // 96768
#define GEMM_SMEM_NT8 ((GBM + 128) * PADW * 4 * 3)   // 110592

// ---------------- RoPE (standalone, R1-proven) ----------------
__global__ void rope_kernel(const float* __restrict__ cosT,
                            const float* __restrict__ sinT)
{
    const int t = blockIdx.x;
    float* row = g_qkv + (size_t)t * QKVC;
    const float* ct = cosT + t * 64;
    const float* st = sinT + t * 64;
    for (int p = threadIdx.x; p < 40 * 32; p += blockDim.x) {
        int hh = p >> 5;
        int dl = p & 31;
        int base = (hh < 32) ? hh * 64 : 2048 + (hh - 32) * 64;
        float lo = row[base + dl];
        float hi = row[base + dl + 32];
        float c0 = ct[dl],      s0 = st[dl];
        float c1 = ct[dl + 32], s1 = st[dl + 32];
        row[base + dl]      = lo * c0 - hi * s0;
        row[base + dl + 32] = hi * c1 + lo * s1;
    }
}

// ---------------- SWA v3 (frozen from R11) ----------------
#define SQ_STR 68
#define SK_STR 68
#define SP_STR 164
#define SV_STR 164
#define NU     160
#define OFF_Q   0
#define OFF_K   4352
#define OFF_P   OFF_K
#define OFF_V   15232
#define OFF_DEN 25728
#define SWA_SMEM ((25728 + 64) * 4)     // 103168 bytes -> 2 CTAs/SM

__global__ __launch_bounds__(256, 2)
void swa_kernel(const float* __restrict__ sinks)
{
    extern __shared__ float sm[];
    const uint32_t sb = smem_u32(sm);
    const int tid = threadIdx.x, lane = tid & 31, wid = tid >> 5;
    const int gid = lane >> 2, tig = lane & 3;
    const int t0  = blockIdx.x * TQ;
    const int kvh = blockIdx.y;

    float* Qs  = sm + OFF_Q;
    float* Ks  = sm + OFF_K;
    float* Vt  = sm + OFF_V;
    float* P   = sm + OFF_P;
    float* den = sm + OFF_DEN;

    for (int idx = tid; idx < NU * 64; idx += 256) {
        int u = idx >> 6, d = idx & 63;
        int j = t0 - 127 + u;
        float kv = 0.f, vv = 0.f;
        if (u <= 142 && j >= 0) {
            const float* r = g_qkv + (size_t)j * QKVC;
            kv = f2tf32f(r[2048 + kvh * 64 + d]);
            vv = f2tf32f(r[2560 + kvh * 64 + d]);
        }
        Ks[u * SK_STR + d] = kv;
        Vt[d * SV_STR + u] = vv;
    }
    for (int idx = tid; idx < 64 * 64; idx += 256) {
        int r = idx >> 6, d = idx & 63;
        int i = r >> 2, g = r & 3;
        Qs[r * SQ_STR + d] = f2tf32f(
            g_qkv[(size_t)(t0 + i) * QKVC + (kvh * 4 + g) * 64 + d] * 0.125f);
    }
    __syncthreads();

    const int q = lane >> 3;
    const int arow = ((q & 1) << 3) + (lane & 7);
    const int akof = (q >> 1) << 2;
    const int brow = ((q >> 1) << 3) + (lane & 7);
    const int bkof = (q & 1) << 2;

    {
        const int mrow = (wid & 3) << 4;
        const int ncol = (wid >> 2) * 80;
        float s[10][4];
#pragma unroll
        for (int nt = 0; nt < 10; nt++)
#pragma unroll
            for (int z = 0; z < 4; z++) s[nt][z] = 0.f;

        const uint32_t Qb = sb + (uint32_t)((OFF_Q + (mrow + arow) * SQ_STR + akof) * 4);
        const uint32_t Kb = sb + (uint32_t)((OFF_K + (ncol + brow) * SK_STR + bkof) * 4);
#pragma unroll
        for (int ks = 0; ks < 8; ks++) {
            const uint32_t kb = ks * 32;
            uint32_t afr[4];
            ldsm_x4(afr, Qb + kb);
            uint32_t bfr[5][4];
#pragma unroll
            for (int p = 0; p < 5; p++)
                ldsm_x4(bfr[p], Kb + kb + (uint32_t)(p * 16 * SK_STR * 4));
#pragma unroll
            for (int p = 0; p < 5; p++) {
                mma_tf32(s[2 * p + 0], afr, &bfr[p][0]);
                mma_tf32(s[2 * p + 1], afr, &bfr[p][2]);
            }
        }
        __syncthreads();
#pragma unroll
        for (int nt = 0; nt < 10; nt++) {
            int col = ncol + nt * 8 + 2 * tig;
            P[(mrow + gid) * SP_STR + col]         = s[nt][0];
            P[(mrow + gid) * SP_STR + col + 1]     = s[nt][1];
            P[(mrow + gid + 8) * SP_STR + col]     = s[nt][2];
            P[(mrow + gid + 8) * SP_STR + col + 1] = s[nt][3];
        }
    }
    __syncthreads();

    {
        const int lim = 127 - t0;
        for (int rr = 0; rr < 8; rr++) {
            int r = wid * 8 + rr;
            int i = r >> 2, g = r & 3;
            int lo = (i > lim) ? i : lim;
            int hi = i + 127;
            float v[5];
#pragma unroll
            for (int c = 0; c < 5; c++) {
                int u = lane + c * 32;
                float x = P[r * SP_STR + u];
                v[c] = (u >= lo && u <= hi) ? x : -1e30f;
            }
            float m = v[0];
#pragma unroll
            for (int c = 1; c < 5; c++) m = fmaxf(m, v[c]);
#pragma unroll
            for (int o = 16; o; o >>= 1)
                m = fmaxf(m, __shfl_xor_sync(0xffffffffu, m, o));
            float snk = __ldg(&sinks[kvh * 4 + g]);
            m = fmaxf(m, snk);
            float sum = 0.f;
#pragma unroll
            for (int c = 0; c < 5; c++) {
                int u = lane + c * 32;
                float e = 0.f;
                if (u >= lo && u <= hi) e = f2tf32f(__expf(v[c] - m));
                P[r * SP_STR + u] = e;
                sum += e;
            }
#pragma unroll
            for (int o = 16; o; o >>= 1)
                sum += __shfl_xor_sync(0xffffffffu, sum, o);
            sum += __expf(snk - m);
            if (lane == 0) den[r] = 1.0f / sum;
        }
    }
    __syncthreads();

    {
        const int mrow = (wid & 3) << 4;
        const int ncol = (wid >> 2) << 5;
        float o[4][4];
#pragma unroll
        for (int nt = 0; nt < 4; nt++)
#pragma unroll
            for (int z = 0; z < 4; z++) o[nt][z] = 0.f;

        const uint32_t Pb = sb + (uint32_t)((OFF_P + (mrow + arow) * SP_STR + akof) * 4);
        const uint32_t Vb = sb + (uint32_t)((OFF_V + (ncol + brow) * SV_STR + bkof) * 4);
#pragma unroll
        for (int ks = 0; ks < 20; ks++) {
            const uint32_t kb = ks * 32;
            uint32_t afr[4];
            ldsm_x4(afr, Pb + kb);
            uint32_t bfr[2][4];
            ldsm_x4(bfr[0], Vb + kb);
            ldsm_x4(bfr[1], Vb + kb + (uint32_t)(16 * SV_STR * 4));
#pragma unroll
            for (int p = 0; p < 2; p++) {
                mma_tf32(o[2 * p + 0], afr, &bfr[p][0]);
                mma_tf32(o[2 * p + 1], afr, &bfr[p][2]);
            }
        }
        int r0 = mrow + gid, r1 = r0 + 8;
        float i0 = den[r0], i1 = den[r1];
        int tA = t0 + (r0 >> 2), chA = (kvh * 4 + (r0 & 3)) * 64;
        int tB = t0 + (r1 >> 2), chB = (kvh * 4 + (r1 & 3)) * 64;
#pragma unroll
        for (int nt = 0; nt < 4; nt++) {
            int col = ncol + nt * 8 + 2 * tig;
            g_attn[(size_t)tA * DIMX + chA + col]     = f2tf32f(o[nt][0] * i0);
            g_attn[(size_t)tA * DIMX + chA + col + 1] = f2tf32f(o[nt][1] * i0);
            g_attn[(size_t)tB * DIMX + chB + col]     = f2tf32f(o[nt][2] * i1);
            g_attn[(size_t)tB * DIMX + chB + col + 1] = f2tf32f(o[nt][3] * i1);
        }
    }
}

// ---------------- host ----------------
extern "C" void kernel_launch(void* const* d_in, const int* in_sizes, int n_in,
                              void* d_out, int out_size)
{
    (void)in_sizes; (void)n_in; (void)out_size;
    const float* x     = (const float*)d_in[0];
    const float* cosT  = (const float*)d_in[1];
    const float* sinT  = (const float*)d_in[2];
    const float* Wqkv  = (const float*)d_in[3];
    const float* bqkv  = (const float*)d_in[4];
    const float* Wo    = (const float*)d_in[5];
    const float* bo    = (const float*)d_in[6];
    const float* sinks = (const float*)d_in[7];
    float* out = (float*)d_out;

    float *qkv = nullptr, *att = nullptr;
    float *xc = nullptr, *wqkvc = nullptr, *woc = nullptr;
    cudaGetSymbolAddress((void**)&qkv,   g_qkv);
    cudaGetSymbolAddress((void**)&att,   g_attn);
    cudaGetSymbolAddress((void**)&xc,    g_xc);
    cudaGetSymbolAddress((void**)&wqkvc, g_wqkvc);
    cudaGetSymbolAddress((void**)&woc,   g_woc);

    cudaFuncSetAttribute(gemm_mma_tf32<6>,
                         cudaFuncAttributeMaxDynamicSharedMemorySize, GEMM_SMEM_NT6);
    cudaFuncSetAttribute(gemm_mma_tf32<8>,
                         cudaFuncAttributeMaxDynamicSharedMemorySize, GEMM_SMEM_NT8);
    cudaFuncSetAttribute(swa_kernel,
                         cudaFuncAttributeMaxDynamicSharedMemorySize, SWA_SMEM);

    // 0) tf32 pre-rounding passes
    cvt_tf32_kernel<<<(T_TOK * DIMX / 4 + 255) / 256, 256>>>(x,    xc,    T_TOK * DIMX / 4);
    cvt_tf32_kernel<<<(QKVC * DIMX / 4 + 255) / 256, 256>>>(Wqkv, wqkvc, QKVC * DIMX / 4);
    cvt_tf32_kernel<<<(DIMX * DIMX / 4 + 255) / 256, 256>>>(Wo,   woc,   DIMX * DIMX / 4);

    // 1) qkv = x @ Wqkv^T + bqkv  (BN=96 -> 512 CTAs, 86% wave util)
    gemm_mma_tf32<6><<<dim3(QKVC / 96, T_TOK / GBM), 256, GEMM_SMEM_NT6>>>(
        xc, wqkvc, bqkv, qkv, QKVC, DIMX);
    // 2) RoPE in-place on q,k
    rope_kernel<<<T_TOK, 256>>>(cosT, sinT);
    // 3) tensorized sliding-window attention with sink (2 CTAs/SM)
    swa_kernel<<<dim3(T_TOK / TQ, NKV), 256, SWA_SMEM>>>(sinks);
    // 4) out = attn @ Wo^T + bo   (BN=128 -> 256 CTAs, 1 wave)
    gemm_mma_tf32<8><<<dim3(DIMX / 128, T_TOK / GBM), 256, GEMM_SMEM_NT8>>>(
        att, woc, bo, out, DIMX, DIMX);
}

// round 14
// speedup vs baseline: 1.3123x; 1.0045x over previous
#include <cuda_runtime.h>
#include <math.h>
#include <cstdint>
#include <cstddef>

// ---------------- problem constants ----------------
#define T_TOK   2048
#define DIMX    2048
#define QKVC    3072      // (32 + 2*8) * 64
#define NKV     8
#define WIN     128
#define TQ      16

// Scratch (no allocs allowed)
__device__ float g_qkv[(size_t)T_TOK * QKVC];
__device__ float g_attn[(size_t)T_TOK * DIMX];
__device__ float g_xc[(size_t)T_TOK * DIMX];      // tf32-rounded x
__device__ float g_wqkvc[(size_t)QKVC * DIMX];    // tf32-rounded Wqkv
__device__ float g_woc[(size_t)DIMX * DIMX];      // tf32-rounded Wo

// ---------------- helpers ----------------
__device__ __forceinline__ uint32_t smem_u32(const void* p) {
    uint32_t a;
    asm("{ .reg .u64 t; cvta.to.shared.u64 t, %1; cvt.u32.u64 %0, t; }"
        : "=r"(a) : "l"(p));
    return a;
}
__device__ __forceinline__ float f2tf32f(float f) {
    uint32_t r;
    asm("cvt.rna.tf32.f32 %0, %1;" : "=r"(r) : "f"(f));
    return __uint_as_float(r);
}
__device__ __forceinline__ void mma_tf32(float* d, const uint32_t* a,
                                         const uint32_t* b) {
    asm volatile(
        "mma.sync.aligned.m16n8k8.row.col.f32.tf32.tf32.f32 "
        "{%0,%1,%2,%3}, {%4,%5,%6,%7}, {%8,%9}, {%0,%1,%2,%3};"
        : "+f"(d[0]), "+f"(d[1]), "+f"(d[2]), "+f"(d[3])
        : "r"(a[0]), "r"(a[1]), "r"(a[2]), "r"(a[3]), "r"(b[0]), "r"(b[1]));
}
__device__ __forceinline__ void ldsm_x4(uint32_t* r, uint32_t addr) {
    asm volatile(
        "ldmatrix.sync.aligned.m8n8.x4.shared.b16 {%0,%1,%2,%3}, [%4];"
        : "=r"(r[0]), "=r"(r[1]), "=r"(r[2]), "=r"(r[3]) : "r"(addr));
}

// ---------------- tf32 pre-round pass ----------------
__global__ void cvt_tf32_kernel(const float* __restrict__ in,
                                float* __restrict__ out, int n4)
{
    int i = blockIdx.x * blockDim.x + threadIdx.x;
    if (i < n4) {
        float4 v = *(const float4*)(in + (size_t)i * 4);
        v.x = f2tf32f(v.x); v.y = f2tf32f(v.y);
        v.z = f2tf32f(v.z); v.w = f2tf32f(v.w);
        *(float4*)(out + (size_t)i * 4) = v;
    }
}

// ---------------- tf32 mma.sync GEMM -----------------------------------------
// C[M, Ntot] = A[M, K] * B[Ntot, K]^T + bias.  Inputs MUST be tf32-pre-rounded.
// CTA tile 128 x (16*NT), BK=32, 256 threads, warp grid 4M x 2N.
// Template: NT = N-tiles per warp (BN = 16*NT), STG = pipeline stages,
//           MB = min blocks per SM (reg budget 65536/(256*MB)).
#define GBM  128
#define GBK  32
#define PADW 36                    // 144B row stride; odd multiple of 16B

template <int NT, int STG, int MB>
__global__ __launch_bounds__(256, MB)
void gemm_mma_tf32(const float* __restrict__ A, const float* __restrict__ B,
                   const float* __restrict__ bias, float* __restrict__ C,
                   int Ntot, int K)
{
    constexpr int BN   = NT * 16;            // CTA N-tile
    constexpr int SSTG = (GBM + BN) * PADW;  // floats per stage

    extern __shared__ float smf[];
    const uint32_t sbase = smem_u32(smf);

    const int tid  = threadIdx.x;
    const int lane = tid & 31;
    const int wid  = tid >> 5;
    const int warpM = wid & 3;
    const int warpN = wid >> 2;
    const int gid = lane >> 2;
    const int tig = lane & 3;

    const int m0 = blockIdx.y * GBM;
    const int n0 = blockIdx.x * BN;
    const int niter = K / GBK;

    const float* Ag = A + (size_t)m0 * K;
    const float* Bg = B + (size_t)n0 * K;

    const int r0 = tid >> 3;
    const int c4 = (tid & 7) * 4;

    const int q = lane >> 3;
    const int arow = ((q & 1) << 3) + (lane & 7);
    const int akof = (q >> 1) << 2;
    const int brow = ((q >> 1) << 3) + (lane & 7);
    const int bkof = (q & 1) << 2;
    const uint32_t a_off = (uint32_t)(((warpM * 32 + arow) * PADW + akof) * 4);
    const uint32_t b_off = (uint32_t)((GBM * PADW + (warpN * NT * 8 + brow) * PADW + bkof) * 4);

    float acc[2][NT][4];
#pragma unroll
    for (int mt = 0; mt < 2; mt++)
#pragma unroll
        for (int nt = 0; nt < NT; nt++)
#pragma unroll
            for (int z = 0; z < 4; z++) acc[mt][nt][z] = 0.f;

    auto issue = [&](int kt, int s) {
        if (kt < niter) {
            uint32_t abase = sbase + (uint32_t)(s * SSTG + r0 * PADW + c4) * 4;
            const float* ap = Ag + (size_t)r0 * K + kt * GBK + c4;
            const float* bp = Bg + (size_t)r0 * K + kt * GBK + c4;
            uint32_t bbase = abase + GBM * PADW * 4;
#pragma unroll
            for (int i = 0; i < 4; i++)
                asm volatile("cp.async.cg.shared.global [%0], [%1], 16;"
                             :: "r"(abase + i * 32 * PADW * 4),
                                "l"(ap + (size_t)i * 32 * K) : "memory");
#pragma unroll
            for (int i = 0; i < BN / 32; i++)
                asm volatile("cp.async.cg.shared.global [%0], [%1], 16;"
                             :: "r"(bbase + i * 32 * PADW * 4),
                                "l"(bp + (size_t)i * 32 * K) : "memory");
        }
        asm volatile("cp.async.commit_group;" ::: "memory");
    };

    issue(0, 0);
    issue(1, 1);

    for (int it = 0; it < niter; it++) {
        asm volatile("cp.async.wait_group 1;" ::: "memory");
        __syncthreads();

        if (STG == 3) issue(it + 2, (it + 2) % 3);   // stage already consumed

        const uint32_t stg = sbase + (uint32_t)((it % STG) * SSTG) * 4;
        const uint32_t aB = stg + a_off;
        const uint32_t bB = stg + b_off;

#pragma unroll
        for (int ks = 0; ks < 4; ks++) {
            const uint32_t kb = ks * 32;
            uint32_t afr[2][4];
            ldsm_x4(afr[0], aB + kb);
            ldsm_x4(afr[1], aB + kb + 16 * PADW * 4);
            uint32_t bfr[NT / 2][4];
#pragma unroll
            for (int p = 0; p < NT / 2; p++)
                ldsm_x4(bfr[p], bB + kb + (uint32_t)(p * 16 * PADW * 4));
#pragma unroll
            for (int mt = 0; mt < 2; mt++)
#pragma unroll
                for (int p = 0; p < NT / 2; p++) {
                    mma_tf32(acc[mt][2 * p + 0], afr[mt], &bfr[p][0]);
                    mma_tf32(acc[mt][2 * p + 1], afr[mt], &bfr[p][2]);
                }
        }

        if (STG == 2) {                               // must finish reads first
            __syncthreads();
            issue(it + 2, (it + 2) & 1);
        }
    }

    // ---- epilogue: bias only ----
#pragma unroll
    for (int mt = 0; mt < 2; mt++) {
        int row = m0 + warpM * 32 + mt * 16 + gid;
#pragma unroll
        for (int nt = 0; nt < NT; nt++) {
            int col = n0 + warpN * NT * 8 + nt * 8 + 2 * tig;
            float b0 = __ldg(&bias[col]);
            float b1 = __ldg(&bias[col + 1]);
            *(float2*)(C + (size_t)row * Ntot + col) =
                make_float2(acc[mt][nt][0] + b0, acc[mt][nt][1] + b1);
            *(float2*)(C + (size_t)(row + 8) * Ntot + col) =
                make_float2(acc[mt][nt][2] + b0, acc[mt][nt][3] + b1);
        }
    }
}

#define GEMM_SMEM_NT6_S2 ((GBM + 96)  * PADW * 4 * 2)   // 64512
#define GEMM_SMEM_NT8_S3 ((GBM + 128) * PADW * 4 * 3)   // 110592

// ---------------- RoPE (standalone, frozen) ----------------
__global__ void rope_kernel(const float* __restrict__ cosT,
                            const float* __restrict__ sinT)
{
    const int t = blockIdx.x;
    float* row = g_qkv + (size_t)t * QKVC;
    const float* ct = cosT + t * 64;
    const float* st = sinT + t * 64;
    for (int p = threadIdx.x; p < 40 * 32; p += blockDim.x) {
        int hh = p >> 5;
        int dl = p & 31;
        int base = (hh < 32) ? hh * 64 : 2048 + (hh - 32) * 64;
        float lo = row[base + dl];
        float hi = row[base + dl + 32];
        float c0 = ct[dl],      s0 = st[dl];
        float c1 = ct[dl + 32], s1 = st[dl + 32];
        row[base + dl]      = lo * c0 - hi * s0;
        row[base + dl + 32] = hi * c1 + lo * s1;
    }
}

// ---------------- SWA v3 (frozen from R11) ----------------
#define SQ_STR 68
#define SK_STR 68
#define SP_STR 164
#define SV_STR 164
#define NU     160
#define OFF_Q   0
#define OFF_K   4352
#define OFF_P   OFF_K
#define OFF_V   15232
#define OFF_DEN 25728
#define SWA_SMEM ((25728 + 64) * 4)     // 103168 bytes -> 2 CTAs/SM

__global__ __launch_bounds__(256, 2)
void swa_kernel(const float* __restrict__ sinks)
{
    extern __shared__ float sm[];
    const uint32_t sb = smem_u32(sm);
    const int tid = threadIdx.x, lane = tid & 31, wid = tid >> 5;
    const int gid = lane >> 2, tig = lane & 3;
    const int t0  = blockIdx.x * TQ;
    const int kvh = blockIdx.y;

    float* Qs  = sm + OFF_Q;
    float* Ks  = sm + OFF_K;
    float* Vt  = sm + OFF_V;
    float* P   = sm + OFF_P;
    float* den = sm + OFF_DEN;

    for (int idx = tid; idx < NU * 64; idx += 256) {
        int u = idx >> 6, d = idx & 63;
        int j = t0 - 127 + u;
        float kv = 0.f, vv = 0.f;
        if (u <= 142 && j >= 0) {
            const float* r = g_qkv + (size_t)j * QKVC;
            kv = f2tf32f(r[2048 + kvh * 64 + d]);
            vv = f2tf32f(r[2560 + kvh * 64 + d]);
        }
        Ks[u * SK_STR + d] = kv;
        Vt[d * SV_STR + u] = vv;
    }
    for (int idx = tid; idx < 64 * 64; idx += 256) {
        int r = idx >> 6, d = idx & 63;
        int i = r >> 2, g = r & 3;
        Qs[r * SQ_STR + d] = f2tf32f(
            g_qkv[(size_t)(t0 + i) * QKVC + (kvh * 4 + g) * 64 + d] * 0.125f);
    }
    __syncthreads();

    const int q = lane >> 3;
    const int arow = ((q & 1) << 3) + (lane & 7);
    const int akof = (q >> 1) << 2;
    const int brow = ((q >> 1) << 3) + (lane & 7);
    const int bkof = (q & 1) << 2;

    {
        const int mrow = (wid & 3) << 4;
        const int ncol = (wid >> 2) * 80;
        float s[10][4];
#pragma unroll
        for (int nt = 0; nt < 10; nt++)
#pragma unroll
            for (int z = 0; z < 4; z++) s[nt][z] = 0.f;

        const uint32_t Qb = sb + (uint32_t)((OFF_Q + (mrow + arow) * SQ_STR + akof) * 4);
        const uint32_t Kb = sb + (uint32_t)((OFF_K + (ncol + brow) * SK_STR + bkof) * 4);
#pragma unroll
        for (int ks = 0; ks < 8; ks++) {
            const uint32_t kb = ks * 32;
            uint32_t afr[4];
            ldsm_x4(afr, Qb + kb);
            uint32_t bfr[5][4];
#pragma unroll
            for (int p = 0; p < 5; p++)
                ldsm_x4(bfr[p], Kb + kb + (uint32_t)(p * 16 * SK_STR * 4));
#pragma unroll
            for (int p = 0; p < 5; p++) {
                mma_tf32(s[2 * p + 0], afr, &bfr[p][0]);
                mma_tf32(s[2 * p + 1], afr, &bfr[p][2]);
            }
        }
        __syncthreads();
#pragma unroll
        for (int nt = 0; nt < 10; nt++) {
            int col = ncol + nt * 8 + 2 * tig;
            P[(mrow + gid) * SP_STR + col]         = s[nt][0];
            P[(mrow + gid) * SP_STR + col + 1]     = s[nt][1];
            P[(mrow + gid + 8) * SP_STR + col]     = s[nt][2];
            P[(mrow + gid + 8) * SP_STR + col + 1] = s[nt][3];
        }
    }
    __syncthreads();

    {
        const int lim = 127 - t0;
        for (int rr = 0; rr < 8; rr++) {
            int r = wid * 8 + rr;
            int i = r >> 2, g = r & 3;
            int lo = (i > lim) ? i : lim;
            int hi = i + 127;
            float v[5];
#pragma unroll
            for (int c = 0; c < 5; c++) {
                int u = lane + c * 32;
                float x = P[r * SP_STR + u];
                v[c] = (u >= lo && u <= hi) ? x : -1e30f;
            }
            float m = v[0];
#pragma unroll
            for (int c = 1; c < 5; c++) m = fmaxf(m, v[c]);
#pragma unroll
            for (int o = 16; o; o >>= 1)
                m = fmaxf(m, __shfl_xor_sync(0xffffffffu, m, o));
            float snk = __ldg(&sinks[kvh * 4 + g]);
            m = fmaxf(m, snk);
            float sum = 0.f;
#pragma unroll
            for (int c = 0; c < 5; c++) {
                int u = lane + c * 32;
                float e = 0.f;
                if (u >= lo && u <= hi) e = f2tf32f(__expf(v[c] - m));
                P[r * SP_STR + u] = e;
                sum += e;
            }
#pragma unroll
            for (int o = 16; o; o >>= 1)
                sum += __shfl_xor_sync(0xffffffffu, sum, o);
            sum += __expf(snk - m);
            if (lane == 0) den[r] = 1.0f / sum;
        }
    }
    __syncthreads();

    {
        const int mrow = (wid & 3) << 4;
        const int ncol = (wid >> 2) << 5;
        float o[4][4];
#pragma unroll
        for (int nt = 0; nt < 4; nt++)
#pragma unroll
            for (int z = 0; z < 4; z++) o[nt][z] = 0.f;

        const uint32_t Pb = sb + (uint32_t)((OFF_P + (mrow + arow) * SP_STR + akof) * 4);
        const uint32_t Vb = sb + (uint32_t)((OFF_V + (ncol + brow) * SV_STR + bkof) * 4);
#pragma unroll
        for (int ks = 0; ks < 20; ks++) {
            const uint32_t kb = ks * 32;
            uint32_t afr[4];
            ldsm_x4(afr, Pb + kb);
            uint32_t bfr[2][4];
            ldsm_x4(bfr[0], Vb + kb);
            ldsm_x4(bfr[1], Vb + kb + (uint32_t)(16 * SV_STR * 4));
#pragma unroll
            for (int p = 0; p < 2; p++) {
                mma_tf32(o[2 * p + 0], afr, &bfr[p][0]);
                mma_tf32(o[2 * p + 1], afr, &bfr[p][2]);
            }
        }
        int r0 = mrow + gid, r1 = r0 + 8;
        float i0 = den[r0], i1 = den[r1];
        int tA = t0 + (r0 >> 2), chA = (kvh * 4 + (r0 & 3)) * 64;
        int tB = t0 + (r1 >> 2), chB = (kvh * 4 + (r1 & 3)) * 64;
#pragma unroll
        for (int nt = 0; nt < 4; nt++) {
            int col = ncol + nt * 8 + 2 * tig;
            g_attn[(size_t)tA * DIMX + chA + col]     = f2tf32f(o[nt][0] * i0);
            g_attn[(size_t)tA * DIMX + chA + col + 1] = f2tf32f(o[nt][1] * i0);
            g_attn[(size_t)tB * DIMX + chB + col]     = f2tf32f(o[nt][2] * i1);
            g_attn[(size_t)tB * DIMX + chB + col + 1] = f2tf32f(o[nt][3] * i1);
        }
    }
}

// ---------------- host ----------------
extern "C" void kernel_launch(void* const* d_in, const int* in_sizes, int n_in,
                              void* d_out, int out_size)
{
    (void)in_sizes; (void)n_in; (void)out_size;
    const float* x     = (const float*)d_in[0];
    const float* cosT  = (const float*)d_in[1];
    const float* sinT  = (const float*)d_in[2];
    const float* Wqkv  = (const float*)d_in[3];
    const float* bqkv  = (const float*)d_in[4];
    const float* Wo    = (const float*)d_in[5];
    const float* bo    = (const float*)d_in[6];
    const float* sinks = (const float*)d_in[7];
    float* out = (float*)d_out;

    float *qkv = nullptr, *att = nullptr;
    float *xc = nullptr, *wqkvc = nullptr, *woc = nullptr;
    cudaGetSymbolAddress((void**)&qkv,   g_qkv);
    cudaGetSymbolAddress((void**)&att,   g_attn);
    cudaGetSymbolAddress((void**)&xc,    g_xc);
    cudaGetSymbolAddress((void**)&wqkvc, g_wqkvc);
    cudaGetSymbolAddress((void**)&woc,   g_woc);

    cudaFuncSetAttribute((const void*)gemm_mma_tf32<6, 2, 3>,
                         cudaFuncAttributeMaxDynamicSharedMemorySize, GEMM_SMEM_NT6_S2);
    cudaFuncSetAttribute((const void*)gemm_mma_tf32<8, 3, 2>,
                         cudaFuncAttributeMaxDynamicSharedMemorySize, GEMM_SMEM_NT8_S3);
    cudaFuncSetAttribute(swa_kernel,
                         cudaFuncAttributeMaxDynamicSharedMemorySize, SWA_SMEM);

    // 0) tf32 pre-rounding passes
    cvt_tf32_kernel<<<(T_TOK * DIMX / 4 + 255) / 256, 256>>>(x,    xc,    T_TOK * DIMX / 4);
    cvt_tf32_kernel<<<(QKVC * DIMX / 4 + 255) / 256, 256>>>(Wqkv, wqkvc, QKVC * DIMX / 4);
    cvt_tf32_kernel<<<(DIMX * DIMX / 4 + 255) / 256, 256>>>(Wo,   woc,   DIMX * DIMX / 4);

    // 1) qkv = x @ Wqkv^T + bqkv  (BN=96, 2-stage, 3 CTAs/SM)
    gemm_mma_tf32<6, 2, 3><<<dim3(QKVC / 96, T_TOK / GBM), 256, GEMM_SMEM_NT6_S2>>>(
        xc, wqkvc, bqkv, qkv, QKVC, DIMX);
    // 2) RoPE in-place on q,k
    rope_kernel<<<T_TOK, 256>>>(cosT, sinT);
    // 3) tensorized sliding-window attention with sink (2 CTAs/SM)
    swa_kernel<<<dim3(T_TOK / TQ, NKV), 256, SWA_SMEM>>>(sinks);
    // 4) out = attn @ Wo^T + bo   (BN=128, 3-stage, 2 CTAs/SM — frozen)
    gemm_mma_tf32<8, 3, 2><<<dim3(DIMX / 128, T_TOK / GBM), 256, GEMM_SMEM_NT8_S3>>>(
        att, woc, bo, out, DIMX, DIMX);
}

// round 15
// speedup vs baseline: 1.7920x; 1.3655x over previous
#include <cuda_runtime.h>
#include <cuda_fp16.h>
#include <math.h>
#include <cstdint>
#include <cstddef>

// ---------------- problem constants ----------------
#define T_TOK   2048
#define DIMX    2048
#define QKVC    3072      // (32 + 2*8) * 64
#define NKV     8
#define WIN     128
#define TQ      16

// Scratch (no allocs allowed)
__device__ float  g_qkv[(size_t)T_TOK * QKVC];        // fp32 qkv (rope in-place)
__device__ __half g_attn_h[(size_t)T_TOK * DIMX];     // fp16 attention output
__device__ __half g_xh[(size_t)T_TOK * DIMX];         // fp16 x
__device__ __half g_wqkvh[(size_t)QKVC * DIMX];       // fp16 Wqkv
__device__ __half g_woh[(size_t)DIMX * DIMX];         // fp16 Wo

// ---------------- helpers ----------------
__device__ __forceinline__ uint32_t smem_u32(const void* p) {
    uint32_t a;
    asm("{ .reg .u64 t; cvta.to.shared.u64 t, %1; cvt.u32.u64 %0, t; }"
        : "=r"(a) : "l"(p));
    return a;
}
__device__ __forceinline__ float f2tf32f(float f) {
    uint32_t r;
    asm("cvt.rna.tf32.f32 %0, %1;" : "=r"(r) : "f"(f));
    return __uint_as_float(r);
}
__device__ __forceinline__ void mma_tf32(float* d, const uint32_t* a,
                                         const uint32_t* b) {
    asm volatile(
        "mma.sync.aligned.m16n8k8.row.col.f32.tf32.tf32.f32 "
        "{%0,%1,%2,%3}, {%4,%5,%6,%7}, {%8,%9}, {%0,%1,%2,%3};"
        : "+f"(d[0]), "+f"(d[1]), "+f"(d[2]), "+f"(d[3])
        : "r"(a[0]), "r"(a[1]), "r"(a[2]), "r"(a[3]), "r"(b[0]), "r"(b[1]));
}
__device__ __forceinline__ void mma_f16(float* d, const uint32_t* a,
                                        uint32_t b0, uint32_t b1) {
    asm volatile(
        "mma.sync.aligned.m16n8k16.row.col.f32.f16.f16.f32 "
        "{%0,%1,%2,%3}, {%4,%5,%6,%7}, {%8,%9}, {%0,%1,%2,%3};"
        : "+f"(d[0]), "+f"(d[1]), "+f"(d[2]), "+f"(d[3])
        : "r"(a[0]), "r"(a[1]), "r"(a[2]), "r"(a[3]), "r"(b0), "r"(b1));
}
__device__ __forceinline__ void ldsm_x4(uint32_t* r, uint32_t addr) {
    asm volatile(
        "ldmatrix.sync.aligned.m8n8.x4.shared.b16 {%0,%1,%2,%3}, [%4];"
        : "=r"(r[0]), "=r"(r[1]), "=r"(r[2]), "=r"(r[3]) : "r"(addr));
}

// ---------------- fp32 -> fp16 pre-convert pass ----------------
__global__ void cvt_f16_kernel(const float* __restrict__ in,
                               __half* __restrict__ out, int n4)
{
    int i = blockIdx.x * blockDim.x + threadIdx.x;
    if (i < n4) {
        float4 v = *(const float4*)(in + (size_t)i * 4);
        __half2 h0 = __floats2half2_rn(v.x, v.y);
        __half2 h1 = __floats2half2_rn(v.z, v.w);
        ((__half2*)out)[2 * i]     = h0;
        ((__half2*)out)[2 * i + 1] = h1;
    }
}

// ---------------- fp16 mma.sync GEMM (m16n8k16, 2x tf32 rate) ---------------
// C[M, Ntot] = A[M, K] * B[Ntot, K]^T + bias.  A, B are fp16, C fp32.
// CTA tile 128 x (16*NT), BK=32 halves, 3-stage cp.async, 256 threads,
// warp grid 4M x 2N.  PADH=40 halves (80 B row stride, odd x16B -> LDSM-clean).
#define GBM  128
#define PADH 40

template <int NT>
__global__ __launch_bounds__(256, 2)
void gemm_mma_f16(const __half* __restrict__ A, const __half* __restrict__ B,
                  const float* __restrict__ bias, float* __restrict__ C,
                  int Ntot, int K)
{
    constexpr int BN   = NT * 16;
    constexpr int ROWS = GBM + BN;
    constexpr int STGB = ROWS * PADH * 2;     // bytes per stage

    extern __shared__ char smc[];
    const uint32_t sbase = smem_u32(smc);

    const int tid  = threadIdx.x;
    const int lane = tid & 31;
    const int wid  = tid >> 5;
    const int warpM = wid & 3;
    const int warpN = wid >> 2;
    const int gid = lane >> 2;
    const int tig = lane & 3;

    const int m0 = blockIdx.y * GBM;
    const int n0 = blockIdx.x * BN;
    const int niter = K / 32;

    const __half* Ag = A + (size_t)m0 * K;
    const __half* Bg = B + (size_t)n0 * K;

    // ldmatrix per-lane: tile order (r0-7,kLo),(r8-15,kLo),(r0-7,kHi),(r8-15,kHi)
    const int q    = lane >> 3;
    const int row8 = ((q & 1) << 3) + (lane & 7);
    const int kofB = (q >> 1) << 4;                 // 0 or 16 bytes
    const uint32_t a_off = (uint32_t)((warpM * 32 + row8) * PADH * 2 + kofB);
    const uint32_t b_off = (uint32_t)((GBM + warpN * NT * 8 + row8) * PADH * 2 + kofB);

    float acc[2][NT][4];
#pragma unroll
    for (int mt = 0; mt < 2; mt++)
#pragma unroll
        for (int nt = 0; nt < NT; nt++)
#pragma unroll
            for (int z = 0; z < 4; z++) acc[mt][nt][z] = 0.f;

    auto issue = [&](int kt, int s) {
        if (kt < niter) {
            for (int c = tid; c < ROWS * 4; c += 256) {
                int row = c >> 2;
                int o8  = (c & 3) * 8;              // halves
                uint32_t dst = sbase + (uint32_t)(s * STGB + row * PADH * 2 + o8 * 2);
                const __half* src = (row < GBM)
                    ? Ag + (size_t)row * K + kt * 32 + o8
                    : Bg + (size_t)(row - GBM) * K + kt * 32 + o8;
                asm volatile("cp.async.cg.shared.global [%0], [%1], 16;"
                             :: "r"(dst), "l"(src) : "memory");
            }
        }
        asm volatile("cp.async.commit_group;" ::: "memory");
    };

    issue(0, 0);
    issue(1, 1);

    for (int it = 0; it < niter; it++) {
        asm volatile("cp.async.wait_group 1;" ::: "memory");
        __syncthreads();
        issue(it + 2, (it + 2) % 3);

        const uint32_t stg = sbase + (uint32_t)((it % 3) * STGB);
        const uint32_t aB = stg + a_off;
        const uint32_t bB = stg + b_off;

#pragma unroll
        for (int ks = 0; ks < 2; ks++) {            // two k16 steps per BK=32
            const uint32_t kb = ks * 32;            // 16 halves = 32 bytes
            uint32_t afr[2][4];
            ldsm_x4(afr[0], aB + kb);
            ldsm_x4(afr[1], aB + kb + 16 * PADH * 2);
            uint32_t bfr[NT / 2][4];
#pragma unroll
            for (int p = 0; p < NT / 2; p++)
                ldsm_x4(bfr[p], bB + kb + (uint32_t)(p * 16 * PADH * 2));
#pragma unroll
            for (int mt = 0; mt < 2; mt++)
#pragma unroll
                for (int p = 0; p < NT / 2; p++) {
                    mma_f16(acc[mt][2 * p + 0], afr[mt], bfr[p][0], bfr[p][2]);
                    mma_f16(acc[mt][2 * p + 1], afr[mt], bfr[p][1], bfr[p][3]);
                }
        }
    }

    // ---- epilogue: bias (fp32 out) ----
#pragma unroll
    for (int mt = 0; mt < 2; mt++) {
        int row = m0 + warpM * 32 + mt * 16 + gid;
#pragma unroll
        for (int nt = 0; nt < NT; nt++) {
            int col = n0 + warpN * NT * 8 + nt * 8 + 2 * tig;
            float b0 = __ldg(&bias[col]);
            float b1 = __ldg(&bias[col + 1]);
            *(float2*)(C + (size_t)row * Ntot + col) =
                make_float2(acc[mt][nt][0] + b0, acc[mt][nt][1] + b1);
            *(float2*)(C + (size_t)(row + 8) * Ntot + col) =
                make_float2(acc[mt][nt][2] + b0, acc[mt][nt][3] + b1);
        }
    }
}

// padded to force 2 CTAs/SM (NT6 natural 3-stage smem is 53.8 KB)
#define GEMM_SMEM_NT6 98304
#define GEMM_SMEM_NT8 ((GBM + 128) * PADH * 2 * 3)   // 61440

// ---------------- RoPE (standalone, frozen) ----------------
__global__ void rope_kernel(const float* __restrict__ cosT,
                            const float* __restrict__ sinT)
{
    const int t = blockIdx.x;
    float* row = g_qkv + (size_t)t * QKVC;
    const float* ct = cosT + t * 64;
    const float* st = sinT + t * 64;
    for (int p = threadIdx.x; p < 40 * 32; p += blockDim.x) {
        int hh = p >> 5;
        int dl = p & 31;
        int base = (hh < 32) ? hh * 64 : 2048 + (hh - 32) * 64;
        float lo = row[base + dl];
        float hi = row[base + dl + 32];
        float c0 = ct[dl],      s0 = st[dl];
        float c1 = ct[dl + 32], s1 = st[dl + 32];
        row[base + dl]      = lo * c0 - hi * s0;
        row[base + dl + 32] = hi * c1 + lo * s1;
    }
}

// ---------------- SWA v3 (frozen core; output now fp16) ----------------
#define SQ_STR 68
#define SK_STR 68
#define SP_STR 164
#define SV_STR 164
#define NU     160
#define OFF_Q   0
#define OFF_K   4352
#define OFF_P   OFF_K
#define OFF_V   15232
#define OFF_DEN 25728
#define SWA_SMEM ((25728 + 64) * 4)     // 103168 bytes -> 2 CTAs/SM

__global__ __launch_bounds__(256, 2)
void swa_kernel(const float* __restrict__ sinks)
{
    extern __shared__ float sm[];
    const uint32_t sb = smem_u32(sm);
    const int tid = threadIdx.x, lane = tid & 31, wid = tid >> 5;
    const int gid = lane >> 2, tig = lane & 3;
    const int t0  = blockIdx.x * TQ;
    const int kvh = blockIdx.y;

    float* Qs  = sm + OFF_Q;
    float* Ks  = sm + OFF_K;
    float* Vt  = sm + OFF_V;
    float* P   = sm + OFF_P;
    float* den = sm + OFF_DEN;

    for (int idx = tid; idx < NU * 64; idx += 256) {
        int u = idx >> 6, d = idx & 63;
        int j = t0 - 127 + u;
        float kv = 0.f, vv = 0.f;
        if (u <= 142 && j >= 0) {
            const float* r = g_qkv + (size_t)j * QKVC;
            kv = f2tf32f(r[2048 + kvh * 64 + d]);
            vv = f2tf32f(r[2560 + kvh * 64 + d]);
        }
        Ks[u * SK_STR + d] = kv;
        Vt[d * SV_STR + u] = vv;
    }
    for (int idx = tid; idx < 64 * 64; idx += 256) {
        int r = idx >> 6, d = idx & 63;
        int i = r >> 2, g = r & 3;
        Qs[r * SQ_STR + d] = f2tf32f(
            g_qkv[(size_t)(t0 + i) * QKVC + (kvh * 4 + g) * 64 + d] * 0.125f);
    }
    __syncthreads();

    const int q = lane >> 3;
    const int arow = ((q & 1) << 3) + (lane & 7);
    const int akof = (q >> 1) << 2;
    const int brow = ((q >> 1) << 3) + (lane & 7);
    const int bkof = (q & 1) << 2;

    {
        const int mrow = (wid & 3) << 4;
        const int ncol = (wid >> 2) * 80;
        float s[10][4];
#pragma unroll
        for (int nt = 0; nt < 10; nt++)
#pragma unroll
            for (int z = 0; z < 4; z++) s[nt][z] = 0.f;

        const uint32_t Qb = sb + (uint32_t)((OFF_Q + (mrow + arow) * SQ_STR + akof) * 4);
        const uint32_t Kb = sb + (uint32_t)((OFF_K + (ncol + brow) * SK_STR + bkof) * 4);
#pragma unroll
        for (int ks = 0; ks < 8; ks++) {
            const uint32_t kb = ks * 32;
            uint32_t afr[4];
            ldsm_x4(afr, Qb + kb);
            uint32_t bfr[5][4];
#pragma unroll
            for (int p = 0; p < 5; p++)
                ldsm_x4(bfr[p], Kb + kb + (uint32_t)(p * 16 * SK_STR * 4));
#pragma unroll
            for (int p = 0; p < 5; p++) {
                mma_tf32(s[2 * p + 0], afr, &bfr[p][0]);
                mma_tf32(s[2 * p + 1], afr, &bfr[p][2]);
            }
        }
        __syncthreads();
#pragma unroll
        for (int nt = 0; nt < 10; nt++) {
            int col = ncol + nt * 8 + 2 * tig;
            P[(mrow + gid) * SP_STR + col]         = s[nt][0];
            P[(mrow + gid) * SP_STR + col + 1]     = s[nt][1];
            P[(mrow + gid + 8) * SP_STR + col]     = s[nt][2];
            P[(mrow + gid + 8) * SP_STR + col + 1] = s[nt][3];
        }
    }
    __syncthreads();

    {
        const int lim = 127 - t0;
        for (int rr = 0; rr < 8; rr++) {
            int r = wid * 8 + rr;
            int i = r >> 2, g = r & 3;
            int lo = (i > lim) ? i : lim;
            int hi = i + 127;
            float v[5];
#pragma unroll
            for (int c = 0; c < 5; c++) {
                int u = lane + c * 32;
                float x = P[r * SP_STR + u];
                v[c] = (u >= lo && u <= hi) ? x : -1e30f;
            }
            float m = v[0];
#pragma unroll
            for (int c = 1; c < 5; c++) m = fmaxf(m, v[c]);
#pragma unroll
            for (int o = 16; o; o >>= 1)
                m = fmaxf(m, __shfl_xor_sync(0xffffffffu, m, o));
            float snk = __ldg(&sinks[kvh * 4 + g]);
            m = fmaxf(m, snk);
            float sum = 0.f;
#pragma unroll
            for (int c = 0; c < 5; c++) {
                int u = lane + c * 32;
                float e = 0.f;
                if (u >= lo && u <= hi) e = f2tf32f(__expf(v[c] - m));
                P[r * SP_STR + u] = e;
                sum += e;
            }
#pragma unroll
            for (int o = 16; o; o >>= 1)
                sum += __shfl_xor_sync(0xffffffffu, sum, o);
            sum += __expf(snk - m);
            if (lane == 0) den[r] = 1.0f / sum;
        }
    }
    __syncthreads();

    {
        const int mrow = (wid & 3) << 4;
        const int ncol = (wid >> 2) << 5;
        float o[4][4];
#pragma unroll
        for (int nt = 0; nt < 4; nt++)
#pragma unroll
            for (int z = 0; z < 4; z++) o[nt][z] = 0.f;

        const uint32_t Pb = sb + (uint32_t)((OFF_P + (mrow + arow) * SP_STR + akof) * 4);
        const uint32_t Vb = sb + (uint32_t)((OFF_V + (ncol + brow) * SV_STR + bkof) * 4);
#pragma unroll
        for (int ks = 0; ks < 20; ks++) {
            const uint32_t kb = ks * 32;
            uint32_t afr[4];
            ldsm_x4(afr, Pb + kb);
            uint32_t bfr[2][4];
            ldsm_x4(bfr[0], Vb + kb);
            ldsm_x4(bfr[1], Vb + kb + (uint32_t)(16 * SV_STR * 4));
#pragma unroll
            for (int p = 0; p < 2; p++) {
                mma_tf32(o[2 * p + 0], afr, &bfr[p][0]);
                mma_tf32(o[2 * p + 1], afr, &bfr[p][2]);
            }
        }
        int r0 = mrow + gid, r1 = r0 + 8;
        float i0 = den[r0], i1 = den[r1];
        int tA = t0 + (r0 >> 2), chA = (kvh * 4 + (r0 & 3)) * 64;
        int tB = t0 + (r1 >> 2), chB = (kvh * 4 + (r1 & 3)) * 64;
#pragma unroll
        for (int nt = 0; nt < 4; nt++) {
            int col = ncol + nt * 8 + 2 * tig;
            *(__half2*)(g_attn_h + (size_t)tA * DIMX + chA + col) =
                __floats2half2_rn(o[nt][0] * i0, o[nt][1] * i0);
            *(__half2*)(g_attn_h + (size_t)tB * DIMX + chB + col) =
                __floats2half2_rn(o[nt][2] * i1, o[nt][3] * i1);
        }
    }
}

// ---------------- host ----------------
extern "C" void kernel_launch(void* const* d_in, const int* in_sizes, int n_in,
                              void* d_out, int out_size)
{
    (void)in_sizes; (void)n_in; (void)out_size;
    const float* x     = (const float*)d_in[0];
    const float* cosT  = (const float*)d_in[1];
    const float* sinT  = (const float*)d_in[2];
    const float* Wqkv  = (const float*)d_in[3];
    const float* bqkv  = (const float*)d_in[4];
    const float* Wo    = (const float*)d_in[5];
    const float* bo    = (const float*)d_in[6];
    const float* sinks = (const float*)d_in[7];
    float* out = (float*)d_out;

    float*  qkv = nullptr;
    __half *xh = nullptr, *wqkvh = nullptr, *woh = nullptr, *attnh = nullptr;
    cudaGetSymbolAddress((void**)&qkv,   g_qkv);
    cudaGetSymbolAddress((void**)&xh,    g_xh);
    cudaGetSymbolAddress((void**)&wqkvh, g_wqkvh);
    cudaGetSymbolAddress((void**)&woh,   g_woh);
    cudaGetSymbolAddress((void**)&attnh, g_attn_h);

    cudaFuncSetAttribute((const void*)gemm_mma_f16<6>,
                         cudaFuncAttributeMaxDynamicSharedMemorySize, GEMM_SMEM_NT6);
    cudaFuncSetAttribute((const void*)gemm_mma_f16<8>,
                         cudaFuncAttributeMaxDynamicSharedMemorySize, GEMM_SMEM_NT8);
    cudaFuncSetAttribute(swa_kernel,
                         cudaFuncAttributeMaxDynamicSharedMemorySize, SWA_SMEM);

    // 0) fp32 -> fp16 pre-convert passes
    cvt_f16_kernel<<<(T_TOK * DIMX / 4 + 255) / 256, 256>>>(x,    xh,    T_TOK * DIMX / 4);
    cvt_f16_kernel<<<(QKVC * DIMX / 4 + 255) / 256, 256>>>(Wqkv, wqkvh, QKVC * DIMX / 4);
    cvt_f16_kernel<<<(DIMX * DIMX / 4 + 255) / 256, 256>>>(Wo,   woh,   DIMX * DIMX / 4);

    // 1) qkv = x @ Wqkv^T + bqkv  (fp16 mma, BN=96 -> 512 CTAs, 2 CTAs/SM)
    gemm_mma_f16<6><<<dim3(QKVC / 96, T_TOK / GBM), 256, GEMM_SMEM_NT6>>>(
        xh, wqkvh, bqkv, qkv, QKVC, DIMX);
    // 2) RoPE in-place on q,k (fp32)
    rope_kernel<<<T_TOK, 256>>>(cosT, sinT);
    // 3) tensorized sliding-window attention with sink (2 CTAs/SM, fp16 out)
    swa_kernel<<<dim3(T_TOK / TQ, NKV), 256, SWA_SMEM>>>(sinks);
    // 4) out = attn @ Wo^T + bo   (fp16 mma, BN=128 -> 256 CTAs)
    gemm_mma_f16<8><<<dim3(DIMX / 128, T_TOK / GBM), 256, GEMM_SMEM_NT8>>>(
        attnh, woh, bo, out, DIMX, DIMX);
}